// round 12
// baseline (speedup 1.0000x reference)
#include <cuda_runtime.h>
#include <cuda_bf16.h>
#include <cstdint>

// ---------------------------------------------------------------------------
// Problem: B=16, S=1024, IN=512, OUT=256.
// out = softmax((x Wq^T)(x Wk^T)^T / sqrt(512)) (x Wv^T)
// RoPE uses ONE fixed rotation per dim-pair applied identically to Q and K;
// 2x2 rotations are orthogonal => (Rq).(Rk) = q.k, and V is unroped, so RoPE
// cancels exactly and is skipped.
//
// GEMM engine: mma.sync.m16n8k16 bf16 (family-portable HMMA).
// Accuracy: 2-term bf16 split (x = hi + lo): accumulate hh + hl + lh in fp32.
//
// R12: (a) pass-outer MMA ordering -- accumulators reused at distance 16, no
// back-to-back C-dependency stalls; (b) softmax replaced by row-stats kernel +
// exp folded into pv's A-tile fill (kills the 128MB softmax round-trip).
// ---------------------------------------------------------------------------
#define BATCH   16
#define SEQ     1024
#define IN_DIM  512
#define OUT_DIM 256

#define THREADS 256
#define BK 16              // fp32 elements per K-chunk

#define ROWB 48            // SMEM row stride bytes (16 bf16 = 32B + 16B pad)
#define TILE_HALF (128 * ROWB)       // one operand-half (hi or lo): 6144 B
#define STAGE_BYTES (4 * TILE_HALF)  // A_hi A_lo B_hi B_lo: 24576 B

#define SCALE 0.044194173824159216f  // 1/sqrt(512)

// ---------------------------------------------------------------------------
// Scratch (device globals; allocations are forbidden)
// ---------------------------------------------------------------------------
__device__ float g_q [BATCH * SEQ * OUT_DIM];          // [b*S+s][d]
__device__ float g_k [BATCH * SEQ * OUT_DIM];          // [b*S+s][d]
__device__ float g_vt[BATCH * OUT_DIM * SEQ];          // [b][d][s]  (V^T)
__device__ float g_s [(size_t)BATCH * SEQ * SEQ];      // scaled scores
__device__ float g_m  [BATCH * SEQ];                   // row max
__device__ float g_inv[BATCH * SEQ];                   // 1 / sum(exp(s - m))

// ---------------------------------------------------------------------------
// Helpers
// ---------------------------------------------------------------------------
__device__ __forceinline__ uint32_t smem_u32(const void* p) {
    uint32_t a;
    asm("{ .reg .u64 t; cvta.to.shared.u64 t, %1; cvt.u32.u64 %0, t; }"
        : "=r"(a) : "l"(p));
    return a;
}

#define LDSM4(R, addr) \
    asm volatile("ldmatrix.sync.aligned.m8n8.x4.shared.b16 {%0,%1,%2,%3}, [%4];" \
        : "=r"((R)[0]), "=r"((R)[1]), "=r"((R)[2]), "=r"((R)[3]) : "r"(addr))

#define MMA16816(C, A, B0, B1) \
    asm volatile( \
        "mma.sync.aligned.m16n8k16.row.col.f32.bf16.bf16.f32 " \
        "{%0,%1,%2,%3}, {%4,%5,%6,%7}, {%8,%9}, {%0,%1,%2,%3};" \
        : "+f"((C)[0]), "+f"((C)[1]), "+f"((C)[2]), "+f"((C)[3]) \
        : "r"((A)[0]), "r"((A)[1]), "r"((A)[2]), "r"((A)[3]), \
          "r"(B0), "r"(B1))

// ---------------------------------------------------------------------------
// Core tile GEMM: acc(128x128, fp32) += A[128 x K] @ B[128 x K]^T
// A, B fp32 row-major (K contiguous). Split-bf16, pass-outer MMA order.
// Warp layout: 8 warps as 2(M) x 4(N); warp tile 64 x 32.
// 2-stage SMEM pipeline, one __syncthreads per chunk.
// EXPA: apply p = exp(v - m) * inv to the A operand during the fill
// (per-thread rows are fixed: (m0,i0) for row r0, (m1,i1) for row r1).
// ---------------------------------------------------------------------------
template <bool EXPA>
__device__ __forceinline__ void gemm_tile(const float* __restrict__ A, int lda,
                                          const float* __restrict__ B, int ldb,
                                          int nchunks, float (&acc)[4][4][4],
                                          float m0, float i0,
                                          float m1, float i1) {
    __shared__ __align__(16) char smem[2 * STAGE_BYTES];   // 48 KB

    const int tid  = threadIdx.x;
    const int lane = tid & 31;
    const int warp = tid >> 5;
    const int wm = (warp >> 2) * 64;    // warp m origin (0 or 64)
    const int wn = (warp & 3) * 32;     // warp n origin (0,32,64,96)

    const uint32_t sb = smem_u32(smem);

    // ldmatrix addresses (stage 0 base; add stage offset when used).
    uint32_t a_addr[4];
    #pragma unroll
    for (int mi = 0; mi < 4; ++mi)
        a_addr[mi] = sb + (uint32_t)((wm + mi * 16 + (lane & 15)) * ROWB
                                     + (lane >> 4) * 16);
    uint32_t b_addr[2];
    #pragma unroll
    for (int p = 0; p < 2; ++p)
        b_addr[p] = sb + 2u * TILE_HALF
                  + (uint32_t)((wn + p * 16 + (lane & 7) + ((lane & 16) ? 8 : 0)) * ROWB
                               + ((lane & 8) ? 16 : 0));

    // Per-thread GMEM/SMEM coordinates for the fill (2 float4 per operand).
    const int r0 = tid >> 2,          f0 = tid & 3;
    const int r1 = (tid + 256) >> 2,  f1 = tid & 3;

    float4 pf[4];  // pf[0..1] = A float4s, pf[2..3] = B float4s

    auto load_pf = [&](int ch) {
        const float* An = A + (size_t)ch * BK;
        const float* Bn = B + (size_t)ch * BK;
        pf[0] = *reinterpret_cast<const float4*>(An + (size_t)r0 * lda + f0 * 4);
        pf[1] = *reinterpret_cast<const float4*>(An + (size_t)r1 * lda + f1 * 4);
        pf[2] = *reinterpret_cast<const float4*>(Bn + (size_t)r0 * ldb + f0 * 4);
        pf[3] = *reinterpret_cast<const float4*>(Bn + (size_t)r1 * ldb + f1 * 4);
    };

    auto store_pf = [&](int st) {
        char* base = smem + st * STAGE_BYTES;
        #pragma unroll
        for (int i = 0; i < 4; ++i) {
            int r = (i & 1) ? r1 : r0;
            char* dst = base + (i < 2 ? 0 : 2 * TILE_HALF) + r * ROWB + f0 * 8;
            float4 v = pf[i];
            if (EXPA && i < 2) {
                float mm = (i == 0) ? m0 : m1;
                float ii = (i == 0) ? i0 : i1;
                v.x = __expf(v.x - mm) * ii;
                v.y = __expf(v.y - mm) * ii;
                v.z = __expf(v.z - mm) * ii;
                v.w = __expf(v.w - mm) * ii;
            }
            __nv_bfloat162 h0 = __floats2bfloat162_rn(v.x, v.y);
            __nv_bfloat162 h1 = __floats2bfloat162_rn(v.z, v.w);
            float2 q0 = __bfloat1622float2(h0);
            float2 q1 = __bfloat1622float2(h1);
            __nv_bfloat162 l0 = __floats2bfloat162_rn(v.x - q0.x, v.y - q0.y);
            __nv_bfloat162 l1 = __floats2bfloat162_rn(v.z - q1.x, v.w - q1.y);
            uint2 hw = make_uint2(*reinterpret_cast<uint32_t*>(&h0),
                                  *reinterpret_cast<uint32_t*>(&h1));
            uint2 lw = make_uint2(*reinterpret_cast<uint32_t*>(&l0),
                                  *reinterpret_cast<uint32_t*>(&l1));
            *reinterpret_cast<uint2*>(dst) = hw;
            *reinterpret_cast<uint2*>(dst + TILE_HALF) = lw;
        }
    };

    // Prologue: stage 0 filled with chunk 0; chunk 1 in flight in registers.
    load_pf(0);
    store_pf(0);
    if (nchunks > 1) load_pf(1);
    __syncthreads();

    #pragma unroll 1
    for (int ch = 0; ch < nchunks; ++ch) {
        const int st = ch & 1;
        const uint32_t soff = (uint32_t)st * STAGE_BYTES;

        // 1) Fragments for this chunk from stage st.
        uint32_t ah[4][4], al[4][4], bh[4][2], bl[4][2];
        #pragma unroll
        for (int mi = 0; mi < 4; ++mi) {
            LDSM4(ah[mi], a_addr[mi] + soff);
            LDSM4(al[mi], a_addr[mi] + soff + TILE_HALF);
        }
        #pragma unroll
        for (int p = 0; p < 2; ++p) {
            uint32_t t[4];
            LDSM4(t, b_addr[p] + soff);
            bh[2*p][0] = t[0]; bh[2*p][1] = t[1];
            bh[2*p+1][0] = t[2]; bh[2*p+1][1] = t[3];
            LDSM4(t, b_addr[p] + soff + TILE_HALF);
            bl[2*p][0] = t[0]; bl[2*p][1] = t[1];
            bl[2*p+1][0] = t[2]; bl[2*p+1][1] = t[3];
        }

        // 2) Convert chunk ch+1 into the other stage (frees pf).
        if (ch + 1 < nchunks) store_pf(st ^ 1);

        // 3) Issue chunk ch+2 LDGs; they drain behind the MMA block.
        if (ch + 2 < nchunks) load_pf(ch + 2);

        // 4) Split MMA, pass-outer order: every accumulator is reused at
        //    distance 16 MMAs -> no back-to-back C-dependency stalls.
        #pragma unroll
        for (int mi = 0; mi < 4; ++mi)
            #pragma unroll
            for (int ni = 0; ni < 4; ++ni)
                MMA16816(acc[mi][ni], ah[mi], bh[ni][0], bh[ni][1]);
        #pragma unroll
        for (int mi = 0; mi < 4; ++mi)
            #pragma unroll
            for (int ni = 0; ni < 4; ++ni)
                MMA16816(acc[mi][ni], ah[mi], bl[ni][0], bl[ni][1]);
        #pragma unroll
        for (int mi = 0; mi < 4; ++mi)
            #pragma unroll
            for (int ni = 0; ni < 4; ++ni)
                MMA16816(acc[mi][ni], al[mi], bh[ni][0], bh[ni][1]);

        // 5) Stage handoff barrier.
        __syncthreads();
    }
}

// Fragment -> (row, col) helpers. C regs: r0,r1 at (row, col..col+1),
// r2,r3 at (row+8, col..col+1).
__device__ __forceinline__ int frag_row(int mi) {
    int lane = threadIdx.x & 31, warp = threadIdx.x >> 5;
    return (warp >> 2) * 64 + mi * 16 + (lane >> 2);
}
__device__ __forceinline__ int frag_col(int ni) {
    int lane = threadIdx.x & 31, warp = threadIdx.x >> 5;
    return (warp & 3) * 32 + ni * 8 + 2 * (lane & 3);
}

// ---------------------------------------------------------------------------
// Kernel 1: fused QKV. A = x[16384,512]; B = W[256,512] (rows = out dim).
// grid (128 mtiles, 2 ntiles, 3 which). which: 0=Q, 1=K, 2=V (stored V^T).
// ---------------------------------------------------------------------------
__global__ void __launch_bounds__(THREADS, 1)
qkv_kernel(const float* __restrict__ x,
           const float* __restrict__ wq, const float* __restrict__ bq,
           const float* __restrict__ wk, const float* __restrict__ bk,
           const float* __restrict__ wv, const float* __restrict__ bv) {
    const int mt = blockIdx.x, nt = blockIdx.y, which = blockIdx.z;
    const float* w    = (which == 0) ? wq : (which == 1) ? wk : wv;
    const float* bias = (which == 0) ? bq : (which == 1) ? bk : bv;

    float acc[4][4][4];
    #pragma unroll
    for (int i = 0; i < 4; ++i)
        #pragma unroll
        for (int j = 0; j < 4; ++j)
            #pragma unroll
            for (int r = 0; r < 4; ++r) acc[i][j][r] = 0.f;

    gemm_tile<false>(x + (size_t)mt * 128 * IN_DIM, IN_DIM,
                     w + (size_t)nt * 128 * IN_DIM, IN_DIM,
                     IN_DIM / BK, acc, 0.f, 0.f, 0.f, 0.f);

    #pragma unroll
    for (int mi = 0; mi < 4; ++mi)
        #pragma unroll
        for (int ni = 0; ni < 4; ++ni) {
            int m0 = mt * 128 + frag_row(mi);
            int n  = nt * 128 + frag_col(ni);
            float b0 = __ldg(bias + n), b1 = __ldg(bias + n + 1);
            if (which == 2) {
                #pragma unroll
                for (int rr = 0; rr < 2; ++rr) {
                    int m = m0 + rr * 8;
                    int b = m >> 10, s = m & 1023;
                    g_vt[((size_t)b * OUT_DIM + n)     * SEQ + s] = acc[mi][ni][2*rr]     + b0;
                    g_vt[((size_t)b * OUT_DIM + n + 1) * SEQ + s] = acc[mi][ni][2*rr + 1] + b1;
                }
            } else {
                float* dst = which ? g_k : g_q;
                float2 v0 = make_float2(acc[mi][ni][0] + b0, acc[mi][ni][1] + b1);
                float2 v1 = make_float2(acc[mi][ni][2] + b0, acc[mi][ni][3] + b1);
                *reinterpret_cast<float2*>(&dst[(size_t)m0 * OUT_DIM + n])       = v0;
                *reinterpret_cast<float2*>(&dst[(size_t)(m0 + 8) * OUT_DIM + n]) = v1;
            }
        }
}

// ---------------------------------------------------------------------------
// Kernel 2: scores = (Q K^T) * SCALE per batch. grid (8, 8, 16).
// ---------------------------------------------------------------------------
__global__ void __launch_bounds__(THREADS, 1)
scores_kernel() {
    const int mt = blockIdx.x, nt = blockIdx.y, b = blockIdx.z;
    float acc[4][4][4];
    #pragma unroll
    for (int i = 0; i < 4; ++i)
        #pragma unroll
        for (int j = 0; j < 4; ++j)
            #pragma unroll
            for (int r = 0; r < 4; ++r) acc[i][j][r] = 0.f;

    gemm_tile<false>(g_q + ((size_t)b * SEQ + mt * 128) * OUT_DIM, OUT_DIM,
                     g_k + ((size_t)b * SEQ + nt * 128) * OUT_DIM, OUT_DIM,
                     OUT_DIM / BK, acc, 0.f, 0.f, 0.f, 0.f);

    #pragma unroll
    for (int mi = 0; mi < 4; ++mi)
        #pragma unroll
        for (int ni = 0; ni < 4; ++ni) {
            int m0 = mt * 128 + frag_row(mi);
            int n  = nt * 128 + frag_col(ni);
            float* base = g_s + (size_t)b * SEQ * SEQ;
            float2 v0 = make_float2(acc[mi][ni][0] * SCALE, acc[mi][ni][1] * SCALE);
            float2 v1 = make_float2(acc[mi][ni][2] * SCALE, acc[mi][ni][3] * SCALE);
            *reinterpret_cast<float2*>(&base[(size_t)m0 * SEQ + n])       = v0;
            *reinterpret_cast<float2*>(&base[(size_t)(m0 + 8) * SEQ + n]) = v1;
        }
}

// ---------------------------------------------------------------------------
// Kernel 3: row stats: g_m = max(row), g_inv = 1/sum(exp(row - max)).
// One 256-thread block per row.
// ---------------------------------------------------------------------------
__global__ void __launch_bounds__(THREADS)
rowstats_kernel() {
    __shared__ float red[8];
    const size_t row = blockIdx.x;
    const float4* p = reinterpret_cast<const float4*>(g_s + row * SEQ);
    float4 v = p[threadIdx.x];

    float mx = fmaxf(fmaxf(v.x, v.y), fmaxf(v.z, v.w));
    #pragma unroll
    for (int o = 16; o > 0; o >>= 1)
        mx = fmaxf(mx, __shfl_xor_sync(0xFFFFFFFFu, mx, o));
    if ((threadIdx.x & 31) == 0) red[threadIdx.x >> 5] = mx;
    __syncthreads();
    float m2 = red[0];
    #pragma unroll
    for (int i = 1; i < 8; ++i) m2 = fmaxf(m2, red[i]);
    __syncthreads();

    float s = __expf(v.x - m2) + __expf(v.y - m2)
            + __expf(v.z - m2) + __expf(v.w - m2);
    #pragma unroll
    for (int o = 16; o > 0; o >>= 1)
        s += __shfl_xor_sync(0xFFFFFFFFu, s, o);
    if ((threadIdx.x & 31) == 0) red[threadIdx.x >> 5] = s;
    __syncthreads();
    if (threadIdx.x == 0) {
        float tot = 0.f;
        #pragma unroll
        for (int i = 0; i < 8; ++i) tot += red[i];
        g_m[row]   = m2;
        g_inv[row] = 1.0f / tot;
    }
}

// ---------------------------------------------------------------------------
// Kernel 4: out = softmax(S) @ V, with exp folded into the A-tile fill.
// A = g_s[1024,1024] (scaled scores); B = V^T[256,1024] per batch.
// grid (8 mtiles, 2 ntiles, 16 batches).
// ---------------------------------------------------------------------------
__global__ void __launch_bounds__(THREADS, 1)
pv_kernel(float* __restrict__ out) {
    const int mt = blockIdx.x, nt = blockIdx.y, b = blockIdx.z;
    float acc[4][4][4];
    #pragma unroll
    for (int i = 0; i < 4; ++i)
        #pragma unroll
        for (int j = 0; j < 4; ++j)
            #pragma unroll
            for (int r = 0; r < 4; ++r) acc[i][j][r] = 0.f;

    // Per-thread fill rows are fixed: r0 = tid>>2, r1 = r0 + 64.
    const int tid = threadIdx.x;
    const size_t rowbase = (size_t)b * SEQ + mt * 128;
    const float m0 = g_m  [rowbase + (tid >> 2)];
    const float i0 = g_inv[rowbase + (tid >> 2)];
    const float m1 = g_m  [rowbase + (tid >> 2) + 64];
    const float i1 = g_inv[rowbase + (tid >> 2) + 64];

    gemm_tile<true>(g_s  + ((size_t)b * SEQ + mt * 128) * SEQ, SEQ,
                    g_vt + ((size_t)b * OUT_DIM + nt * 128) * SEQ, SEQ,
                    SEQ / BK, acc, m0, i0, m1, i1);

    #pragma unroll
    for (int mi = 0; mi < 4; ++mi)
        #pragma unroll
        for (int ni = 0; ni < 4; ++ni) {
            int m0r = mt * 128 + frag_row(mi);
            int n   = nt * 128 + frag_col(ni);
            float* base = out + (size_t)b * SEQ * OUT_DIM;
            float2 v0 = make_float2(acc[mi][ni][0], acc[mi][ni][1]);
            float2 v1 = make_float2(acc[mi][ni][2], acc[mi][ni][3]);
            *reinterpret_cast<float2*>(&base[(size_t)m0r * OUT_DIM + n])       = v0;
            *reinterpret_cast<float2*>(&base[(size_t)(m0r + 8) * OUT_DIM + n]) = v1;
        }
}

// ---------------------------------------------------------------------------
// Launcher
// ---------------------------------------------------------------------------
extern "C" void kernel_launch(void* const* d_in, const int* in_sizes, int n_in,
                              void* d_out, int out_size) {
    (void)in_sizes; (void)n_in; (void)out_size;
    const float* x  = (const float*)d_in[0];
    const float* wq = (const float*)d_in[1];
    const float* bq = (const float*)d_in[2];
    const float* wk = (const float*)d_in[3];
    const float* bk = (const float*)d_in[4];
    const float* wv = (const float*)d_in[5];
    const float* bv = (const float*)d_in[6];
    float* out = (float*)d_out;

    qkv_kernel<<<dim3(128, 2, 3), THREADS>>>(x, wq, bq, wk, bk, wv, bv);
    scores_kernel<<<dim3(8, 8, 16), THREADS>>>();
    rowstats_kernel<<<BATCH * SEQ, THREADS>>>();
    pv_kernel<<<dim3(8, 2, 16), THREADS>>>(out);
}

// round 13
// speedup vs baseline: 1.1374x; 1.1374x over previous
#include <cuda_runtime.h>
#include <cuda_bf16.h>
#include <cuda_fp16.h>
#include <cstdint>

// ---------------------------------------------------------------------------
// Problem: B=16, S=1024, IN=512, OUT=256.
// out = softmax((x Wq^T)(x Wk^T)^T / sqrt(512)) (x Wv^T)
// RoPE uses ONE fixed rotation per dim-pair applied identically to Q and K;
// 2x2 rotations are orthogonal => (Rq).(Rk) = q.k, and V is unroped, so RoPE
// cancels exactly and is skipped.
//
// qkv/scores: mma.sync m16n8k16 bf16, 2-term split (hh+hl+lh) -> ~1e-5.
// pv:        mma.sync m16n8k16 fp16, single pass (P in [0,1], V ~ O(1))
//            -> ~3e-4 norm rel err; softmax folded into the A-tile fill.
// ---------------------------------------------------------------------------
#define BATCH   16
#define SEQ     1024
#define IN_DIM  512
#define OUT_DIM 256

#define THREADS 256
#define BK 16              // fp32 elements per K-chunk

#define ROWB 48            // SMEM row stride bytes (16 elems*2B = 32B + 16B pad)
#define TILE_HALF (128 * ROWB)       // one 128x16 b16 tile: 6144 B
#define STAGE_BYTES (4 * TILE_HALF)  // split path: A_hi A_lo B_hi B_lo
#define STAGE_PV    (2 * TILE_HALF)  // pv path: A B

#define SCALE 0.044194173824159216f  // 1/sqrt(512)

// ---------------------------------------------------------------------------
// Scratch (device globals; allocations are forbidden)
// ---------------------------------------------------------------------------
__device__ float  g_q  [BATCH * SEQ * OUT_DIM];        // [b*S+s][d]
__device__ float  g_k  [BATCH * SEQ * OUT_DIM];        // [b*S+s][d]
__device__ __half g_vth[BATCH * OUT_DIM * SEQ];        // [b][d][s]  (V^T, fp16)
__device__ float  g_s  [(size_t)BATCH * SEQ * SEQ];    // scaled scores
__device__ float  g_m  [BATCH * SEQ];                  // row max
__device__ float  g_inv[BATCH * SEQ];                  // 1 / sum(exp(s - m))

// ---------------------------------------------------------------------------
// Helpers
// ---------------------------------------------------------------------------
__device__ __forceinline__ uint32_t smem_u32(const void* p) {
    uint32_t a;
    asm("{ .reg .u64 t; cvta.to.shared.u64 t, %1; cvt.u32.u64 %0, t; }"
        : "=r"(a) : "l"(p));
    return a;
}

#define LDSM4(R, addr) \
    asm volatile("ldmatrix.sync.aligned.m8n8.x4.shared.b16 {%0,%1,%2,%3}, [%4];" \
        : "=r"((R)[0]), "=r"((R)[1]), "=r"((R)[2]), "=r"((R)[3]) : "r"(addr))

#define MMA16816_BF16(C, A, B0, B1) \
    asm volatile( \
        "mma.sync.aligned.m16n8k16.row.col.f32.bf16.bf16.f32 " \
        "{%0,%1,%2,%3}, {%4,%5,%6,%7}, {%8,%9}, {%0,%1,%2,%3};" \
        : "+f"((C)[0]), "+f"((C)[1]), "+f"((C)[2]), "+f"((C)[3]) \
        : "r"((A)[0]), "r"((A)[1]), "r"((A)[2]), "r"((A)[3]), \
          "r"(B0), "r"(B1))

#define MMA16816_F16(C, A, B0, B1) \
    asm volatile( \
        "mma.sync.aligned.m16n8k16.row.col.f32.f16.f16.f32 " \
        "{%0,%1,%2,%3}, {%4,%5,%6,%7}, {%8,%9}, {%0,%1,%2,%3};" \
        : "+f"((C)[0]), "+f"((C)[1]), "+f"((C)[2]), "+f"((C)[3]) \
        : "r"((A)[0]), "r"((A)[1]), "r"((A)[2]), "r"((A)[3]), \
          "r"(B0), "r"(B1))

// ---------------------------------------------------------------------------
// Split-bf16 tile GEMM: acc(128x128) += A[128xK] @ B[128xK]^T  (hh+hl+lh)
// Warp layout: 8 warps as 2(M) x 4(N); warp tile 64 x 32.
// 2-stage SMEM pipeline, one __syncthreads per chunk. (R11 MMA ordering.)
// ---------------------------------------------------------------------------
__device__ __forceinline__ void gemm_tile(const float* __restrict__ A, int lda,
                                          const float* __restrict__ B, int ldb,
                                          int nchunks, float (&acc)[4][4][4]) {
    __shared__ __align__(16) char smem[2 * STAGE_BYTES];   // 48 KB

    const int tid  = threadIdx.x;
    const int lane = tid & 31;
    const int warp = tid >> 5;
    const int wm = (warp >> 2) * 64;
    const int wn = (warp & 3) * 32;

    const uint32_t sb = smem_u32(smem);

    uint32_t a_addr[4];
    #pragma unroll
    for (int mi = 0; mi < 4; ++mi)
        a_addr[mi] = sb + (uint32_t)((wm + mi * 16 + (lane & 15)) * ROWB
                                     + (lane >> 4) * 16);
    uint32_t b_addr[2];
    #pragma unroll
    for (int p = 0; p < 2; ++p)
        b_addr[p] = sb + 2u * TILE_HALF
                  + (uint32_t)((wn + p * 16 + (lane & 7) + ((lane & 16) ? 8 : 0)) * ROWB
                               + ((lane & 8) ? 16 : 0));

    const int r0 = tid >> 2,          f0 = tid & 3;
    const int r1 = (tid + 256) >> 2;

    float4 pf[4];

    auto load_pf = [&](int ch) {
        const float* An = A + (size_t)ch * BK;
        const float* Bn = B + (size_t)ch * BK;
        pf[0] = *reinterpret_cast<const float4*>(An + (size_t)r0 * lda + f0 * 4);
        pf[1] = *reinterpret_cast<const float4*>(An + (size_t)r1 * lda + f0 * 4);
        pf[2] = *reinterpret_cast<const float4*>(Bn + (size_t)r0 * ldb + f0 * 4);
        pf[3] = *reinterpret_cast<const float4*>(Bn + (size_t)r1 * ldb + f0 * 4);
    };

    auto store_pf = [&](int st) {
        char* base = smem + st * STAGE_BYTES;
        #pragma unroll
        for (int i = 0; i < 4; ++i) {
            int r = (i & 1) ? r1 : r0;
            char* dst = base + (i < 2 ? 0 : 2 * TILE_HALF) + r * ROWB + f0 * 8;
            float4 v = pf[i];
            __nv_bfloat162 h0 = __floats2bfloat162_rn(v.x, v.y);
            __nv_bfloat162 h1 = __floats2bfloat162_rn(v.z, v.w);
            float2 q0 = __bfloat1622float2(h0);
            float2 q1 = __bfloat1622float2(h1);
            __nv_bfloat162 l0 = __floats2bfloat162_rn(v.x - q0.x, v.y - q0.y);
            __nv_bfloat162 l1 = __floats2bfloat162_rn(v.z - q1.x, v.w - q1.y);
            uint2 hw = make_uint2(*reinterpret_cast<uint32_t*>(&h0),
                                  *reinterpret_cast<uint32_t*>(&h1));
            uint2 lw = make_uint2(*reinterpret_cast<uint32_t*>(&l0),
                                  *reinterpret_cast<uint32_t*>(&l1));
            *reinterpret_cast<uint2*>(dst) = hw;
            *reinterpret_cast<uint2*>(dst + TILE_HALF) = lw;
        }
    };

    load_pf(0);
    store_pf(0);
    if (nchunks > 1) load_pf(1);
    __syncthreads();

    #pragma unroll 1
    for (int ch = 0; ch < nchunks; ++ch) {
        const int st = ch & 1;
        const uint32_t soff = (uint32_t)st * STAGE_BYTES;

        uint32_t ah[4][4], al[4][4], bh[4][2], bl[4][2];
        #pragma unroll
        for (int mi = 0; mi < 4; ++mi) {
            LDSM4(ah[mi], a_addr[mi] + soff);
            LDSM4(al[mi], a_addr[mi] + soff + TILE_HALF);
        }
        #pragma unroll
        for (int p = 0; p < 2; ++p) {
            uint32_t t[4];
            LDSM4(t, b_addr[p] + soff);
            bh[2*p][0] = t[0]; bh[2*p][1] = t[1];
            bh[2*p+1][0] = t[2]; bh[2*p+1][1] = t[3];
            LDSM4(t, b_addr[p] + soff + TILE_HALF);
            bl[2*p][0] = t[0]; bl[2*p][1] = t[1];
            bl[2*p+1][0] = t[2]; bl[2*p+1][1] = t[3];
        }

        if (ch + 1 < nchunks) store_pf(st ^ 1);
        if (ch + 2 < nchunks) load_pf(ch + 2);

        #pragma unroll
        for (int mi = 0; mi < 4; ++mi)
            #pragma unroll
            for (int ni = 0; ni < 4; ++ni) {
                MMA16816_BF16(acc[mi][ni], ah[mi], bh[ni][0], bh[ni][1]);
                MMA16816_BF16(acc[mi][ni], ah[mi], bl[ni][0], bl[ni][1]);
                MMA16816_BF16(acc[mi][ni], al[mi], bh[ni][0], bh[ni][1]);
            }

        __syncthreads();
    }
}

// ---------------------------------------------------------------------------
// pv tile GEMM (single-pass fp16): acc += P[128xK] @ V^T[128xK]^T
// P produced on the fly: p = exp(s - m) * inv, from fp32 scores.
// V^T already fp16 in GMEM (straight copy into SMEM).
// ---------------------------------------------------------------------------
__device__ __forceinline__ void gemm_tile_pv(const float* __restrict__ A, int lda,
                                             const __half* __restrict__ B, int ldb,
                                             int nchunks, float (&acc)[4][4][4],
                                             float m0, float i0,
                                             float m1, float i1) {
    __shared__ __align__(16) char smem[2 * STAGE_PV];   // 24 KB

    const int tid  = threadIdx.x;
    const int lane = tid & 31;
    const int warp = tid >> 5;
    const int wm = (warp >> 2) * 64;
    const int wn = (warp & 3) * 32;

    const uint32_t sb = smem_u32(smem);

    uint32_t a_addr[4];
    #pragma unroll
    for (int mi = 0; mi < 4; ++mi)
        a_addr[mi] = sb + (uint32_t)((wm + mi * 16 + (lane & 15)) * ROWB
                                     + (lane >> 4) * 16);
    uint32_t b_addr[2];
    #pragma unroll
    for (int p = 0; p < 2; ++p)
        b_addr[p] = sb + (uint32_t)TILE_HALF
                  + (uint32_t)((wn + p * 16 + (lane & 7) + ((lane & 16) ? 8 : 0)) * ROWB
                               + ((lane & 8) ? 16 : 0));

    const int r0 = tid >> 2,          f0 = tid & 3;
    const int r1 = (tid + 256) >> 2;

    float4 pfa[2];
    uint2  pfb[2];

    auto load_pf = [&](int ch) {
        const float*  An = A + (size_t)ch * BK;
        const __half* Bn = B + (size_t)ch * BK;
        pfa[0] = *reinterpret_cast<const float4*>(An + (size_t)r0 * lda + f0 * 4);
        pfa[1] = *reinterpret_cast<const float4*>(An + (size_t)r1 * lda + f0 * 4);
        pfb[0] = *reinterpret_cast<const uint2*>(
                     reinterpret_cast<const char*>(Bn + (size_t)r0 * ldb) + f0 * 8);
        pfb[1] = *reinterpret_cast<const uint2*>(
                     reinterpret_cast<const char*>(Bn + (size_t)r1 * ldb) + f0 * 8);
    };

    auto store_pf = [&](int st) {
        char* base = smem + st * STAGE_PV;
        #pragma unroll
        for (int i = 0; i < 2; ++i) {
            int r = i ? r1 : r0;
            float mm = i ? m1 : m0;
            float ii = i ? i1 : i0;
            float4 v = pfa[i];
            v.x = __expf(v.x - mm) * ii;
            v.y = __expf(v.y - mm) * ii;
            v.z = __expf(v.z - mm) * ii;
            v.w = __expf(v.w - mm) * ii;
            __half2 h0 = __floats2half2_rn(v.x, v.y);
            __half2 h1 = __floats2half2_rn(v.z, v.w);
            uint2 hw = make_uint2(*reinterpret_cast<uint32_t*>(&h0),
                                  *reinterpret_cast<uint32_t*>(&h1));
            *reinterpret_cast<uint2*>(base + r * ROWB + f0 * 8) = hw;
            *reinterpret_cast<uint2*>(base + TILE_HALF + r * ROWB + f0 * 8) = pfb[i];
        }
    };

    load_pf(0);
    store_pf(0);
    if (nchunks > 1) load_pf(1);
    __syncthreads();

    #pragma unroll 1
    for (int ch = 0; ch < nchunks; ++ch) {
        const int st = ch & 1;
        const uint32_t soff = (uint32_t)st * STAGE_PV;

        uint32_t ah[4][4], bh[4][2];
        #pragma unroll
        for (int mi = 0; mi < 4; ++mi)
            LDSM4(ah[mi], a_addr[mi] + soff);
        #pragma unroll
        for (int p = 0; p < 2; ++p) {
            uint32_t t[4];
            LDSM4(t, b_addr[p] + soff);
            bh[2*p][0] = t[0]; bh[2*p][1] = t[1];
            bh[2*p+1][0] = t[2]; bh[2*p+1][1] = t[3];
        }

        if (ch + 1 < nchunks) store_pf(st ^ 1);
        if (ch + 2 < nchunks) load_pf(ch + 2);

        #pragma unroll
        for (int mi = 0; mi < 4; ++mi)
            #pragma unroll
            for (int ni = 0; ni < 4; ++ni)
                MMA16816_F16(acc[mi][ni], ah[mi], bh[ni][0], bh[ni][1]);

        __syncthreads();
    }
}

// Fragment -> (row, col) helpers.
__device__ __forceinline__ int frag_row(int mi) {
    int lane = threadIdx.x & 31, warp = threadIdx.x >> 5;
    return (warp >> 2) * 64 + mi * 16 + (lane >> 2);
}
__device__ __forceinline__ int frag_col(int ni) {
    int lane = threadIdx.x & 31, warp = threadIdx.x >> 5;
    return (warp & 3) * 32 + ni * 8 + 2 * (lane & 3);
}

// ---------------------------------------------------------------------------
// Kernel 1: fused QKV. grid (128, 2, 3); which: 0=Q, 1=K, 2=V (stored V^T fp16)
// ---------------------------------------------------------------------------
__global__ void __launch_bounds__(THREADS, 1)
qkv_kernel(const float* __restrict__ x,
           const float* __restrict__ wq, const float* __restrict__ bq,
           const float* __restrict__ wk, const float* __restrict__ bk,
           const float* __restrict__ wv, const float* __restrict__ bv) {
    const int mt = blockIdx.x, nt = blockIdx.y, which = blockIdx.z;
    const float* w    = (which == 0) ? wq : (which == 1) ? wk : wv;
    const float* bias = (which == 0) ? bq : (which == 1) ? bk : bv;

    float acc[4][4][4];
    #pragma unroll
    for (int i = 0; i < 4; ++i)
        #pragma unroll
        for (int j = 0; j < 4; ++j)
            #pragma unroll
            for (int r = 0; r < 4; ++r) acc[i][j][r] = 0.f;

    gemm_tile(x + (size_t)mt * 128 * IN_DIM, IN_DIM,
              w + (size_t)nt * 128 * IN_DIM, IN_DIM,
              IN_DIM / BK, acc);

    #pragma unroll
    for (int mi = 0; mi < 4; ++mi)
        #pragma unroll
        for (int ni = 0; ni < 4; ++ni) {
            int m0 = mt * 128 + frag_row(mi);
            int n  = nt * 128 + frag_col(ni);
            float b0 = __ldg(bias + n), b1 = __ldg(bias + n + 1);
            if (which == 2) {
                #pragma unroll
                for (int rr = 0; rr < 2; ++rr) {
                    int m = m0 + rr * 8;
                    int b = m >> 10, s = m & 1023;
                    g_vth[((size_t)b * OUT_DIM + n)     * SEQ + s] =
                        __float2half(acc[mi][ni][2*rr]     + b0);
                    g_vth[((size_t)b * OUT_DIM + n + 1) * SEQ + s] =
                        __float2half(acc[mi][ni][2*rr + 1] + b1);
                }
            } else {
                float* dst = which ? g_k : g_q;
                float2 v0 = make_float2(acc[mi][ni][0] + b0, acc[mi][ni][1] + b1);
                float2 v1 = make_float2(acc[mi][ni][2] + b0, acc[mi][ni][3] + b1);
                *reinterpret_cast<float2*>(&dst[(size_t)m0 * OUT_DIM + n])       = v0;
                *reinterpret_cast<float2*>(&dst[(size_t)(m0 + 8) * OUT_DIM + n]) = v1;
            }
        }
}

// ---------------------------------------------------------------------------
// Kernel 2: scores = (Q K^T) * SCALE per batch. grid (8, 8, 16).
// ---------------------------------------------------------------------------
__global__ void __launch_bounds__(THREADS, 1)
scores_kernel() {
    const int mt = blockIdx.x, nt = blockIdx.y, b = blockIdx.z;
    float acc[4][4][4];
    #pragma unroll
    for (int i = 0; i < 4; ++i)
        #pragma unroll
        for (int j = 0; j < 4; ++j)
            #pragma unroll
            for (int r = 0; r < 4; ++r) acc[i][j][r] = 0.f;

    gemm_tile(g_q + ((size_t)b * SEQ + mt * 128) * OUT_DIM, OUT_DIM,
              g_k + ((size_t)b * SEQ + nt * 128) * OUT_DIM, OUT_DIM,
              OUT_DIM / BK, acc);

    #pragma unroll
    for (int mi = 0; mi < 4; ++mi)
        #pragma unroll
        for (int ni = 0; ni < 4; ++ni) {
            int m0 = mt * 128 + frag_row(mi);
            int n  = nt * 128 + frag_col(ni);
            float* base = g_s + (size_t)b * SEQ * SEQ;
            float2 v0 = make_float2(acc[mi][ni][0] * SCALE, acc[mi][ni][1] * SCALE);
            float2 v1 = make_float2(acc[mi][ni][2] * SCALE, acc[mi][ni][3] * SCALE);
            *reinterpret_cast<float2*>(&base[(size_t)m0 * SEQ + n])       = v0;
            *reinterpret_cast<float2*>(&base[(size_t)(m0 + 8) * SEQ + n]) = v1;
        }
}

// ---------------------------------------------------------------------------
// Kernel 3: row stats: g_m = max(row), g_inv = 1/sum(exp(row - max)).
// ---------------------------------------------------------------------------
__global__ void __launch_bounds__(THREADS)
rowstats_kernel() {
    __shared__ float red[8];
    const size_t row = blockIdx.x;
    const float4* p = reinterpret_cast<const float4*>(g_s + row * SEQ);
    float4 v = p[threadIdx.x];

    float mx = fmaxf(fmaxf(v.x, v.y), fmaxf(v.z, v.w));
    #pragma unroll
    for (int o = 16; o > 0; o >>= 1)
        mx = fmaxf(mx, __shfl_xor_sync(0xFFFFFFFFu, mx, o));
    if ((threadIdx.x & 31) == 0) red[threadIdx.x >> 5] = mx;
    __syncthreads();
    float m2 = red[0];
    #pragma unroll
    for (int i = 1; i < 8; ++i) m2 = fmaxf(m2, red[i]);
    __syncthreads();

    float s = __expf(v.x - m2) + __expf(v.y - m2)
            + __expf(v.z - m2) + __expf(v.w - m2);
    #pragma unroll
    for (int o = 16; o > 0; o >>= 1)
        s += __shfl_xor_sync(0xFFFFFFFFu, s, o);
    if ((threadIdx.x & 31) == 0) red[threadIdx.x >> 5] = s;
    __syncthreads();
    if (threadIdx.x == 0) {
        float tot = 0.f;
        #pragma unroll
        for (int i = 0; i < 8; ++i) tot += red[i];
        g_m[row]   = m2;
        g_inv[row] = 1.0f / tot;
    }
}

// ---------------------------------------------------------------------------
// Kernel 4: out = softmax(S) @ V, exp folded into A fill, fp16 single pass.
// grid (8 mtiles, 2 ntiles, 16 batches).
// ---------------------------------------------------------------------------
__global__ void __launch_bounds__(THREADS, 2)
pv_kernel(float* __restrict__ out) {
    const int mt = blockIdx.x, nt = blockIdx.y, b = blockIdx.z;
    float acc[4][4][4];
    #pragma unroll
    for (int i = 0; i < 4; ++i)
        #pragma unroll
        for (int j = 0; j < 4; ++j)
            #pragma unroll
            for (int r = 0; r < 4; ++r) acc[i][j][r] = 0.f;

    const int tid = threadIdx.x;
    const size_t rowbase = (size_t)b * SEQ + mt * 128;
    const float m0 = g_m  [rowbase + (tid >> 2)];
    const float i0 = g_inv[rowbase + (tid >> 2)];
    const float m1 = g_m  [rowbase + (tid >> 2) + 64];
    const float i1 = g_inv[rowbase + (tid >> 2) + 64];

    gemm_tile_pv(g_s   + ((size_t)b * SEQ + mt * 128) * SEQ, SEQ,
                 g_vth + ((size_t)b * OUT_DIM + nt * 128) * SEQ, SEQ,
                 SEQ / BK, acc, m0, i0, m1, i1);

    #pragma unroll
    for (int mi = 0; mi < 4; ++mi)
        #pragma unroll
        for (int ni = 0; ni < 4; ++ni) {
            int m0r = mt * 128 + frag_row(mi);
            int n   = nt * 128 + frag_col(ni);
            float* base = out + (size_t)b * SEQ * OUT_DIM;
            float2 v0 = make_float2(acc[mi][ni][0], acc[mi][ni][1]);
            float2 v1 = make_float2(acc[mi][ni][2], acc[mi][ni][3]);
            *reinterpret_cast<float2*>(&base[(size_t)m0r * OUT_DIM + n])       = v0;
            *reinterpret_cast<float2*>(&base[(size_t)(m0r + 8) * OUT_DIM + n]) = v1;
        }
}

// ---------------------------------------------------------------------------
// Launcher
// ---------------------------------------------------------------------------
extern "C" void kernel_launch(void* const* d_in, const int* in_sizes, int n_in,
                              void* d_out, int out_size) {
    (void)in_sizes; (void)n_in; (void)out_size;
    const float* x  = (const float*)d_in[0];
    const float* wq = (const float*)d_in[1];
    const float* bq = (const float*)d_in[2];
    const float* wk = (const float*)d_in[3];
    const float* bk = (const float*)d_in[4];
    const float* wv = (const float*)d_in[5];
    const float* bv = (const float*)d_in[6];
    float* out = (float*)d_out;

    qkv_kernel<<<dim3(128, 2, 3), THREADS>>>(x, wq, bq, wk, bk, wv, bv);
    scores_kernel<<<dim3(8, 8, 16), THREADS>>>();
    rowstats_kernel<<<BATCH * SEQ, THREADS>>>();
    pv_kernel<<<dim3(8, 2, 16), THREADS>>>(out);
}

// round 14
// speedup vs baseline: 1.3230x; 1.1631x over previous
#include <cuda_runtime.h>
#include <cuda_fp16.h>
#include <cstdint>

// ---------------------------------------------------------------------------
// Problem: B=16, S=1024, IN=512, OUT=256.
// out = softmax((x Wq^T)(x Wk^T)^T / sqrt(512)) (x Wv^T)
// RoPE uses ONE fixed rotation per dim-pair applied identically to Q and K;
// 2x2 rotations are orthogonal => (Rq).(Rk) = q.k, and V is unroped, so RoPE
// cancels exactly and is skipped.
//
// qkv/scores: mma.sync m16n8k16 fp16, 2-pass split A (a1+a2 exact), single
//             fp16 B -> only B's 2^-12 rounding survives (~1e-4).
// pv:         single-pass fp16 (P in [0,1]); softmax folded into A fill.
// scores stored fp16 (g_sh) -> halves DRAM traffic of scores/rowstats/pv.
// ---------------------------------------------------------------------------
#define BATCH   16
#define SEQ     1024
#define IN_DIM  512
#define OUT_DIM 256

#define THREADS 256
#define BK 16              // K elements per chunk

#define ROWB 48            // SMEM row stride bytes (16 elems*2B = 32B + 16B pad)
#define TILE_HALF (128 * ROWB)        // one 128x16 b16 tile: 6144 B
#define STAGE_SPLIT (3 * TILE_HALF)   // A1 A2 B : 18432 B
#define STAGE_PV    (2 * TILE_HALF)   // A B     : 12288 B

#define SCALE 0.044194173824159216f   // 1/sqrt(512)

// ---------------------------------------------------------------------------
// Scratch (device globals; allocations are forbidden)
// ---------------------------------------------------------------------------
__device__ float  g_q  [BATCH * SEQ * OUT_DIM];        // [b*S+s][d]
__device__ float  g_k  [BATCH * SEQ * OUT_DIM];        // [b*S+s][d]
__device__ __half g_vth[BATCH * OUT_DIM * SEQ];        // [b][d][s]  (V^T fp16)
__device__ __half g_sh [(size_t)BATCH * SEQ * SEQ];    // scaled scores (fp16)
__device__ float  g_m  [BATCH * SEQ];                  // row max
__device__ float  g_inv[BATCH * SEQ];                  // 1 / sum(exp(s - m))

// ---------------------------------------------------------------------------
// Helpers
// ---------------------------------------------------------------------------
__device__ __forceinline__ uint32_t smem_u32(const void* p) {
    uint32_t a;
    asm("{ .reg .u64 t; cvta.to.shared.u64 t, %1; cvt.u32.u64 %0, t; }"
        : "=r"(a) : "l"(p));
    return a;
}

#define LDSM4(R, addr) \
    asm volatile("ldmatrix.sync.aligned.m8n8.x4.shared.b16 {%0,%1,%2,%3}, [%4];" \
        : "=r"((R)[0]), "=r"((R)[1]), "=r"((R)[2]), "=r"((R)[3]) : "r"(addr))

#define MMA16816_F16(C, A, B0, B1) \
    asm volatile( \
        "mma.sync.aligned.m16n8k16.row.col.f32.f16.f16.f32 " \
        "{%0,%1,%2,%3}, {%4,%5,%6,%7}, {%8,%9}, {%0,%1,%2,%3};" \
        : "+f"((C)[0]), "+f"((C)[1]), "+f"((C)[2]), "+f"((C)[3]) \
        : "r"((A)[0]), "r"((A)[1]), "r"((A)[2]), "r"((A)[3]), \
          "r"(B0), "r"(B1))

// fp32 -> (a1, a2) fp16 split, packed pairwise.
__device__ __forceinline__ void split_f16(float x, float y,
                                          uint32_t& hi, uint32_t& lo) {
    __half2 h = __floats2half2_rn(x, y);
    float2 q = __half22float2(h);
    __half2 l = __floats2half2_rn(x - q.x, y - q.y);
    hi = *reinterpret_cast<uint32_t*>(&h);
    lo = *reinterpret_cast<uint32_t*>(&l);
}

// ---------------------------------------------------------------------------
// Split-fp16 tile GEMM: acc(128x128) += A[128xK] @ B[128xK]^T
//   2 passes: a1*b + a2*b (A split exact; B single fp16).
// Warp layout: 8 warps as 2(M) x 4(N); warp tile 64 x 32.
// 2-stage SMEM pipeline, one __syncthreads per chunk.
// ---------------------------------------------------------------------------
__device__ __forceinline__ void gemm_tile(const float* __restrict__ A, int lda,
                                          const float* __restrict__ B, int ldb,
                                          int nchunks, float (&acc)[4][4][4]) {
    __shared__ __align__(16) char smem[2 * STAGE_SPLIT];   // 36 KB

    const int tid  = threadIdx.x;
    const int lane = tid & 31;
    const int warp = tid >> 5;
    const int wm = (warp >> 2) * 64;
    const int wn = (warp & 3) * 32;

    const uint32_t sb = smem_u32(smem);

    uint32_t a_addr[4];
    #pragma unroll
    for (int mi = 0; mi < 4; ++mi)
        a_addr[mi] = sb + (uint32_t)((wm + mi * 16 + (lane & 15)) * ROWB
                                     + (lane >> 4) * 16);
    uint32_t b_addr[2];
    #pragma unroll
    for (int p = 0; p < 2; ++p)
        b_addr[p] = sb + 2u * TILE_HALF
                  + (uint32_t)((wn + p * 16 + (lane & 7) + ((lane & 16) ? 8 : 0)) * ROWB
                               + ((lane & 8) ? 16 : 0));

    const int r0 = tid >> 2,          f0 = tid & 3;
    const int r1 = (tid + 256) >> 2;

    float4 pf[4];   // pf[0..1]=A rows r0,r1 ; pf[2..3]=B rows r0,r1

    auto load_pf = [&](int ch) {
        const float* An = A + (size_t)ch * BK;
        const float* Bn = B + (size_t)ch * BK;
        pf[0] = *reinterpret_cast<const float4*>(An + (size_t)r0 * lda + f0 * 4);
        pf[1] = *reinterpret_cast<const float4*>(An + (size_t)r1 * lda + f0 * 4);
        pf[2] = *reinterpret_cast<const float4*>(Bn + (size_t)r0 * ldb + f0 * 4);
        pf[3] = *reinterpret_cast<const float4*>(Bn + (size_t)r1 * ldb + f0 * 4);
    };

    auto store_pf = [&](int st) {
        char* base = smem + st * STAGE_SPLIT;
        // A rows: split into a1 (tile 0) + a2 (tile 1).
        #pragma unroll
        for (int i = 0; i < 2; ++i) {
            int r = i ? r1 : r0;
            float4 v = pf[i];
            uint32_t h0, l0, h1, l1;
            split_f16(v.x, v.y, h0, l0);
            split_f16(v.z, v.w, h1, l1);
            char* dst = base + r * ROWB + f0 * 8;
            *reinterpret_cast<uint2*>(dst)             = make_uint2(h0, h1);
            *reinterpret_cast<uint2*>(dst + TILE_HALF) = make_uint2(l0, l1);
        }
        // B rows: single fp16 (tile 2).
        #pragma unroll
        for (int i = 2; i < 4; ++i) {
            int r = (i == 3) ? r1 : r0;
            float4 v = pf[i];
            __half2 h0 = __floats2half2_rn(v.x, v.y);
            __half2 h1 = __floats2half2_rn(v.z, v.w);
            *reinterpret_cast<uint2*>(base + 2 * TILE_HALF + r * ROWB + f0 * 8) =
                make_uint2(*reinterpret_cast<uint32_t*>(&h0),
                           *reinterpret_cast<uint32_t*>(&h1));
        }
    };

    load_pf(0);
    store_pf(0);
    if (nchunks > 1) load_pf(1);
    __syncthreads();

    #pragma unroll 1
    for (int ch = 0; ch < nchunks; ++ch) {
        const int st = ch & 1;
        const uint32_t soff = (uint32_t)st * STAGE_SPLIT;

        uint32_t a1[4][4], a2[4][4], bf[4][2];
        #pragma unroll
        for (int mi = 0; mi < 4; ++mi) {
            LDSM4(a1[mi], a_addr[mi] + soff);
            LDSM4(a2[mi], a_addr[mi] + soff + TILE_HALF);
        }
        #pragma unroll
        for (int p = 0; p < 2; ++p) {
            uint32_t t[4];
            LDSM4(t, b_addr[p] + soff);
            bf[2*p][0] = t[0]; bf[2*p][1] = t[1];
            bf[2*p+1][0] = t[2]; bf[2*p+1][1] = t[3];
        }

        if (ch + 1 < nchunks) store_pf(st ^ 1);
        if (ch + 2 < nchunks) load_pf(ch + 2);

        #pragma unroll
        for (int mi = 0; mi < 4; ++mi)
            #pragma unroll
            for (int ni = 0; ni < 4; ++ni) {
                MMA16816_F16(acc[mi][ni], a1[mi], bf[ni][0], bf[ni][1]);
                MMA16816_F16(acc[mi][ni], a2[mi], bf[ni][0], bf[ni][1]);
            }

        __syncthreads();
    }
}

// ---------------------------------------------------------------------------
// pv tile GEMM (single-pass fp16): acc += P[128xK] @ V^T[128xK]^T
// A = fp16 scores, p = exp(s - m)*inv computed in the fill.
// B = fp16 V^T, raw copy.
// Fill geometry: thread t covers row t>>1, 16B segment t&1, for both tiles.
// ---------------------------------------------------------------------------
__device__ __forceinline__ void gemm_tile_pv(const __half* __restrict__ A, int lda,
                                             const __half* __restrict__ B, int ldb,
                                             int nchunks, float (&acc)[4][4][4],
                                             float mrow, float irow) {
    __shared__ __align__(16) char smem[2 * STAGE_PV];   // 24 KB

    const int tid  = threadIdx.x;
    const int lane = tid & 31;
    const int warp = tid >> 5;
    const int wm = (warp >> 2) * 64;
    const int wn = (warp & 3) * 32;

    const uint32_t sb = smem_u32(smem);

    uint32_t a_addr[4];
    #pragma unroll
    for (int mi = 0; mi < 4; ++mi)
        a_addr[mi] = sb + (uint32_t)((wm + mi * 16 + (lane & 15)) * ROWB
                                     + (lane >> 4) * 16);
    uint32_t b_addr[2];
    #pragma unroll
    for (int p = 0; p < 2; ++p)
        b_addr[p] = sb + (uint32_t)TILE_HALF
                  + (uint32_t)((wn + p * 16 + (lane & 7) + ((lane & 16) ? 8 : 0)) * ROWB
                               + ((lane & 8) ? 16 : 0));

    const int fr = tid >> 1;       // row 0..127
    const int fs = tid & 1;        // 16-byte segment

    uint4 pfa, pfb;

    auto load_pf = [&](int ch) {
        const __half* An = A + (size_t)ch * BK;
        const __half* Bn = B + (size_t)ch * BK;
        pfa = *reinterpret_cast<const uint4*>(An + (size_t)fr * lda + fs * 8);
        pfb = *reinterpret_cast<const uint4*>(Bn + (size_t)fr * ldb + fs * 8);
    };

    auto store_pf = [&](int st) {
        char* base = smem + st * STAGE_PV;
        // A: p = exp(s - m) * inv on 8 halves.
        uint32_t w[4] = {pfa.x, pfa.y, pfa.z, pfa.w};
        #pragma unroll
        for (int j = 0; j < 4; ++j) {
            __half2 h = *reinterpret_cast<__half2*>(&w[j]);
            float2 f = __half22float2(h);
            f.x = __expf(f.x - mrow) * irow;
            f.y = __expf(f.y - mrow) * irow;
            __half2 o = __floats2half2_rn(f.x, f.y);
            w[j] = *reinterpret_cast<uint32_t*>(&o);
        }
        *reinterpret_cast<uint4*>(base + fr * ROWB + fs * 16) =
            make_uint4(w[0], w[1], w[2], w[3]);
        // B: raw copy.
        *reinterpret_cast<uint4*>(base + TILE_HALF + fr * ROWB + fs * 16) = pfb;
    };

    load_pf(0);
    store_pf(0);
    if (nchunks > 1) load_pf(1);
    __syncthreads();

    #pragma unroll 1
    for (int ch = 0; ch < nchunks; ++ch) {
        const int st = ch & 1;
        const uint32_t soff = (uint32_t)st * STAGE_PV;

        uint32_t ah[4][4], bh[4][2];
        #pragma unroll
        for (int mi = 0; mi < 4; ++mi)
            LDSM4(ah[mi], a_addr[mi] + soff);
        #pragma unroll
        for (int p = 0; p < 2; ++p) {
            uint32_t t[4];
            LDSM4(t, b_addr[p] + soff);
            bh[2*p][0] = t[0]; bh[2*p][1] = t[1];
            bh[2*p+1][0] = t[2]; bh[2*p+1][1] = t[3];
        }

        if (ch + 1 < nchunks) store_pf(st ^ 1);
        if (ch + 2 < nchunks) load_pf(ch + 2);

        #pragma unroll
        for (int mi = 0; mi < 4; ++mi)
            #pragma unroll
            for (int ni = 0; ni < 4; ++ni)
                MMA16816_F16(acc[mi][ni], ah[mi], bh[ni][0], bh[ni][1]);

        __syncthreads();
    }
}

// Fragment -> (row, col) helpers.
__device__ __forceinline__ int frag_row(int mi) {
    int lane = threadIdx.x & 31, warp = threadIdx.x >> 5;
    return (warp >> 2) * 64 + mi * 16 + (lane >> 2);
}
__device__ __forceinline__ int frag_col(int ni) {
    int lane = threadIdx.x & 31, warp = threadIdx.x >> 5;
    return (warp & 3) * 32 + ni * 8 + 2 * (lane & 3);
}

// ---------------------------------------------------------------------------
// Kernel 1: fused QKV. grid (128, 2, 3); which: 0=Q, 1=K, 2=V (stored V^T fp16)
// ---------------------------------------------------------------------------
__global__ void __launch_bounds__(THREADS, 1)
qkv_kernel(const float* __restrict__ x,
           const float* __restrict__ wq, const float* __restrict__ bq,
           const float* __restrict__ wk, const float* __restrict__ bk,
           const float* __restrict__ wv, const float* __restrict__ bv) {
    const int mt = blockIdx.x, nt = blockIdx.y, which = blockIdx.z;
    const float* w    = (which == 0) ? wq : (which == 1) ? wk : wv;
    const float* bias = (which == 0) ? bq : (which == 1) ? bk : bv;

    float acc[4][4][4];
    #pragma unroll
    for (int i = 0; i < 4; ++i)
        #pragma unroll
        for (int j = 0; j < 4; ++j)
            #pragma unroll
            for (int r = 0; r < 4; ++r) acc[i][j][r] = 0.f;

    gemm_tile(x + (size_t)mt * 128 * IN_DIM, IN_DIM,
              w + (size_t)nt * 128 * IN_DIM, IN_DIM,
              IN_DIM / BK, acc);

    #pragma unroll
    for (int mi = 0; mi < 4; ++mi)
        #pragma unroll
        for (int ni = 0; ni < 4; ++ni) {
            int m0 = mt * 128 + frag_row(mi);
            int n  = nt * 128 + frag_col(ni);
            float b0 = __ldg(bias + n), b1 = __ldg(bias + n + 1);
            if (which == 2) {
                #pragma unroll
                for (int rr = 0; rr < 2; ++rr) {
                    int m = m0 + rr * 8;
                    int b = m >> 10, s = m & 1023;
                    g_vth[((size_t)b * OUT_DIM + n)     * SEQ + s] =
                        __float2half(acc[mi][ni][2*rr]     + b0);
                    g_vth[((size_t)b * OUT_DIM + n + 1) * SEQ + s] =
                        __float2half(acc[mi][ni][2*rr + 1] + b1);
                }
            } else {
                float* dst = which ? g_k : g_q;
                float2 v0 = make_float2(acc[mi][ni][0] + b0, acc[mi][ni][1] + b1);
                float2 v1 = make_float2(acc[mi][ni][2] + b0, acc[mi][ni][3] + b1);
                *reinterpret_cast<float2*>(&dst[(size_t)m0 * OUT_DIM + n])       = v0;
                *reinterpret_cast<float2*>(&dst[(size_t)(m0 + 8) * OUT_DIM + n]) = v1;
            }
        }
}

// ---------------------------------------------------------------------------
// Kernel 2: scores = (Q K^T) * SCALE per batch, stored fp16. grid (8, 8, 16).
// ---------------------------------------------------------------------------
__global__ void __launch_bounds__(THREADS, 1)
scores_kernel() {
    const int mt = blockIdx.x, nt = blockIdx.y, b = blockIdx.z;
    float acc[4][4][4];
    #pragma unroll
    for (int i = 0; i < 4; ++i)
        #pragma unroll
        for (int j = 0; j < 4; ++j)
            #pragma unroll
            for (int r = 0; r < 4; ++r) acc[i][j][r] = 0.f;

    gemm_tile(g_q + ((size_t)b * SEQ + mt * 128) * OUT_DIM, OUT_DIM,
              g_k + ((size_t)b * SEQ + nt * 128) * OUT_DIM, OUT_DIM,
              OUT_DIM / BK, acc);

    #pragma unroll
    for (int mi = 0; mi < 4; ++mi)
        #pragma unroll
        for (int ni = 0; ni < 4; ++ni) {
            int m0 = mt * 128 + frag_row(mi);
            int n  = nt * 128 + frag_col(ni);
            __half* base = g_sh + (size_t)b * SEQ * SEQ;
            __half2 v0 = __floats2half2_rn(acc[mi][ni][0] * SCALE,
                                           acc[mi][ni][1] * SCALE);
            __half2 v1 = __floats2half2_rn(acc[mi][ni][2] * SCALE,
                                           acc[mi][ni][3] * SCALE);
            *reinterpret_cast<__half2*>(&base[(size_t)m0 * SEQ + n])       = v0;
            *reinterpret_cast<__half2*>(&base[(size_t)(m0 + 8) * SEQ + n]) = v1;
        }
}

// ---------------------------------------------------------------------------
// Kernel 3: row stats from fp16 scores: g_m = max(row), g_inv = 1/sum(exp).
// ---------------------------------------------------------------------------
__global__ void __launch_bounds__(THREADS)
rowstats_kernel() {
    __shared__ float red[8];
    const size_t row = blockIdx.x;
    const uint2* p = reinterpret_cast<const uint2*>(g_sh + row * SEQ);
    uint2 u = p[threadIdx.x];
    __half2 h0 = *reinterpret_cast<__half2*>(&u.x);
    __half2 h1 = *reinterpret_cast<__half2*>(&u.y);
    float2 a = __half22float2(h0);
    float2 c = __half22float2(h1);

    float mx = fmaxf(fmaxf(a.x, a.y), fmaxf(c.x, c.y));
    #pragma unroll
    for (int o = 16; o > 0; o >>= 1)
        mx = fmaxf(mx, __shfl_xor_sync(0xFFFFFFFFu, mx, o));
    if ((threadIdx.x & 31) == 0) red[threadIdx.x >> 5] = mx;
    __syncthreads();
    float m2 = red[0];
    #pragma unroll
    for (int i = 1; i < 8; ++i) m2 = fmaxf(m2, red[i]);
    __syncthreads();

    float s = __expf(a.x - m2) + __expf(a.y - m2)
            + __expf(c.x - m2) + __expf(c.y - m2);
    #pragma unroll
    for (int o = 16; o > 0; o >>= 1)
        s += __shfl_xor_sync(0xFFFFFFFFu, s, o);
    if ((threadIdx.x & 31) == 0) red[threadIdx.x >> 5] = s;
    __syncthreads();
    if (threadIdx.x == 0) {
        float tot = 0.f;
        #pragma unroll
        for (int i = 0; i < 8; ++i) tot += red[i];
        g_m[row]   = m2;
        g_inv[row] = 1.0f / tot;
    }
}

// ---------------------------------------------------------------------------
// Kernel 4: out = softmax(S) @ V, exp folded into A fill, fp16 single pass.
// grid (8 mtiles, 2 ntiles, 16 batches).
// ---------------------------------------------------------------------------
__global__ void __launch_bounds__(THREADS, 2)
pv_kernel(float* __restrict__ out) {
    const int mt = blockIdx.x, nt = blockIdx.y, b = blockIdx.z;
    float acc[4][4][4];
    #pragma unroll
    for (int i = 0; i < 4; ++i)
        #pragma unroll
        for (int j = 0; j < 4; ++j)
            #pragma unroll
            for (int r = 0; r < 4; ++r) acc[i][j][r] = 0.f;

    // Fill row for this thread is fixed: fr = tid >> 1.
    const int tid = threadIdx.x;
    const size_t rowbase = (size_t)b * SEQ + mt * 128;
    const float mrow = g_m  [rowbase + (tid >> 1)];
    const float irow = g_inv[rowbase + (tid >> 1)];

    gemm_tile_pv(g_sh  + ((size_t)b * SEQ + mt * 128) * SEQ, SEQ,
                 g_vth + ((size_t)b * OUT_DIM + nt * 128) * SEQ, SEQ,
                 SEQ / BK, acc, mrow, irow);

    #pragma unroll
    for (int mi = 0; mi < 4; ++mi)
        #pragma unroll
        for (int ni = 0; ni < 4; ++ni) {
            int m0r = mt * 128 + frag_row(mi);
            int n   = nt * 128 + frag_col(ni);
            float* base = out + (size_t)b * SEQ * OUT_DIM;
            float2 v0 = make_float2(acc[mi][ni][0], acc[mi][ni][1]);
            float2 v1 = make_float2(acc[mi][ni][2], acc[mi][ni][3]);
            *reinterpret_cast<float2*>(&base[(size_t)m0r * OUT_DIM + n])       = v0;
            *reinterpret_cast<float2*>(&base[(size_t)(m0r + 8) * OUT_DIM + n]) = v1;
        }
}

// ---------------------------------------------------------------------------
// Launcher
// ---------------------------------------------------------------------------
extern "C" void kernel_launch(void* const* d_in, const int* in_sizes, int n_in,
                              void* d_out, int out_size) {
    (void)in_sizes; (void)n_in; (void)out_size;
    const float* x  = (const float*)d_in[0];
    const float* wq = (const float*)d_in[1];
    const float* bq = (const float*)d_in[2];
    const float* wk = (const float*)d_in[3];
    const float* bk = (const float*)d_in[4];
    const float* wv = (const float*)d_in[5];
    const float* bv = (const float*)d_in[6];
    float* out = (float*)d_out;

    qkv_kernel<<<dim3(128, 2, 3), THREADS>>>(x, wq, bq, wk, bk, wv, bv);
    scores_kernel<<<dim3(8, 8, 16), THREADS>>>();
    rowstats_kernel<<<BATCH * SEQ, THREADS>>>();
    pv_kernel<<<dim3(8, 2, 16), THREADS>>>(out);
}

// round 15
// speedup vs baseline: 1.4121x; 1.0673x over previous
#include <cuda_runtime.h>
#include <cuda_fp16.h>
#include <cstdint>

// ---------------------------------------------------------------------------
// Problem: B=16, S=1024, IN=512, OUT=256.
// out = softmax((x Wq^T)(x Wk^T)^T / sqrt(512)) (x Wv^T)
// RoPE uses ONE fixed rotation per dim-pair applied identically to Q and K;
// 2x2 rotations are orthogonal => (Rq).(Rk) = q.k, and V is unroped, so RoPE
// cancels exactly and is skipped.
//
// qkv:    fp32 loads, split-A fp16 2-pass (exact A, B rounded 2^-12).
//         Epilogue stores q as EXACT fp16 hi/lo pair, k and V^T as fp16.
// scores: 128x256 tile, raw fp16 streams: A = (q1,q2) split, B = k fp16.
// pv:     128x256 tile, single-pass fp16; softmax folded into A fill.
// ---------------------------------------------------------------------------
#define BATCH   16
#define SEQ     1024
#define IN_DIM  512
#define OUT_DIM 256

#define THREADS 256
#define BK 16              // K elements per chunk

#define ROWB 48            // SMEM row stride bytes (16 elems*2B = 32B + 16B pad)
#define T128 (128 * ROWB)             // 128-row b16 tile: 6144 B
#define T256 (256 * ROWB)             // 256-row b16 tile: 12288 B
#define STAGE_QKV (3 * T128)          // A1 A2 B : 18432 B
#define STAGE_SC  (2 * T128 + T256)   // A1 A2 B256 : 24576 B
#define STAGE_PV  (T128 + T256)       // A B256 : 18432 B

#define SCALE 0.044194173824159216f   // 1/sqrt(512)

// ---------------------------------------------------------------------------
// Scratch (device globals; allocations are forbidden)
// ---------------------------------------------------------------------------
__device__ __half g_q1 [BATCH * SEQ * OUT_DIM];        // q hi (fp16)
__device__ __half g_q2 [BATCH * SEQ * OUT_DIM];        // q lo (fp16), q1+q2==q
__device__ __half g_kh [BATCH * SEQ * OUT_DIM];        // k (fp16)
__device__ __half g_vth[BATCH * OUT_DIM * SEQ];        // [b][d][s]  (V^T fp16)
__device__ __half g_sh [(size_t)BATCH * SEQ * SEQ];    // scaled scores (fp16)
__device__ float  g_m  [BATCH * SEQ];                  // row max
__device__ float  g_inv[BATCH * SEQ];                  // 1 / sum(exp(s - m))

// ---------------------------------------------------------------------------
// Helpers
// ---------------------------------------------------------------------------
__device__ __forceinline__ uint32_t smem_u32(const void* p) {
    uint32_t a;
    asm("{ .reg .u64 t; cvta.to.shared.u64 t, %1; cvt.u32.u64 %0, t; }"
        : "=r"(a) : "l"(p));
    return a;
}

#define LDSM4(R, addr) \
    asm volatile("ldmatrix.sync.aligned.m8n8.x4.shared.b16 {%0,%1,%2,%3}, [%4];" \
        : "=r"((R)[0]), "=r"((R)[1]), "=r"((R)[2]), "=r"((R)[3]) : "r"(addr))

#define MMA16816_F16(C, A, B0, B1) \
    asm volatile( \
        "mma.sync.aligned.m16n8k16.row.col.f32.f16.f16.f32 " \
        "{%0,%1,%2,%3}, {%4,%5,%6,%7}, {%8,%9}, {%0,%1,%2,%3};" \
        : "+f"((C)[0]), "+f"((C)[1]), "+f"((C)[2]), "+f"((C)[3]) \
        : "r"((A)[0]), "r"((A)[1]), "r"((A)[2]), "r"((A)[3]), \
          "r"(B0), "r"(B1))

__device__ __forceinline__ void split_f16(float x, float y,
                                          uint32_t& hi, uint32_t& lo) {
    __half2 h = __floats2half2_rn(x, y);
    float2 q = __half22float2(h);
    __half2 l = __floats2half2_rn(x - q.x, y - q.y);
    hi = *reinterpret_cast<uint32_t*>(&h);
    lo = *reinterpret_cast<uint32_t*>(&l);
}

// ===========================================================================
// qkv GEMM (128x128): A fp32 split on the fly, B fp32 -> fp16. (R14 engine)
// Warp layout 2(M) x 4(N), warp tile 64x32.
// ===========================================================================
__device__ __forceinline__ void gemm_tile(const float* __restrict__ A, int lda,
                                          const float* __restrict__ B, int ldb,
                                          int nchunks, float (&acc)[4][4][4]) {
    __shared__ __align__(16) char smem[2 * STAGE_QKV];   // 36 KB

    const int tid  = threadIdx.x;
    const int lane = tid & 31;
    const int warp = tid >> 5;
    const int wm = (warp >> 2) * 64;
    const int wn = (warp & 3) * 32;

    const uint32_t sb = smem_u32(smem);

    uint32_t a_addr[4];
    #pragma unroll
    for (int mi = 0; mi < 4; ++mi)
        a_addr[mi] = sb + (uint32_t)((wm + mi * 16 + (lane & 15)) * ROWB
                                     + (lane >> 4) * 16);
    uint32_t b_addr[2];
    #pragma unroll
    for (int p = 0; p < 2; ++p)
        b_addr[p] = sb + 2u * T128
                  + (uint32_t)((wn + p * 16 + (lane & 7) + ((lane & 16) ? 8 : 0)) * ROWB
                               + ((lane & 8) ? 16 : 0));

    const int r0 = tid >> 2,          f0 = tid & 3;
    const int r1 = (tid + 256) >> 2;

    float4 pf[4];

    auto load_pf = [&](int ch) {
        const float* An = A + (size_t)ch * BK;
        const float* Bn = B + (size_t)ch * BK;
        pf[0] = *reinterpret_cast<const float4*>(An + (size_t)r0 * lda + f0 * 4);
        pf[1] = *reinterpret_cast<const float4*>(An + (size_t)r1 * lda + f0 * 4);
        pf[2] = *reinterpret_cast<const float4*>(Bn + (size_t)r0 * ldb + f0 * 4);
        pf[3] = *reinterpret_cast<const float4*>(Bn + (size_t)r1 * ldb + f0 * 4);
    };

    auto store_pf = [&](int st) {
        char* base = smem + st * STAGE_QKV;
        #pragma unroll
        for (int i = 0; i < 2; ++i) {
            int r = i ? r1 : r0;
            float4 v = pf[i];
            uint32_t h0, l0, h1, l1;
            split_f16(v.x, v.y, h0, l0);
            split_f16(v.z, v.w, h1, l1);
            char* dst = base + r * ROWB + f0 * 8;
            *reinterpret_cast<uint2*>(dst)        = make_uint2(h0, h1);
            *reinterpret_cast<uint2*>(dst + T128) = make_uint2(l0, l1);
        }
        #pragma unroll
        for (int i = 2; i < 4; ++i) {
            int r = (i == 3) ? r1 : r0;
            float4 v = pf[i];
            __half2 h0 = __floats2half2_rn(v.x, v.y);
            __half2 h1 = __floats2half2_rn(v.z, v.w);
            *reinterpret_cast<uint2*>(base + 2 * T128 + r * ROWB + f0 * 8) =
                make_uint2(*reinterpret_cast<uint32_t*>(&h0),
                           *reinterpret_cast<uint32_t*>(&h1));
        }
    };

    load_pf(0);
    store_pf(0);
    if (nchunks > 1) load_pf(1);
    __syncthreads();

    #pragma unroll 1
    for (int ch = 0; ch < nchunks; ++ch) {
        const int st = ch & 1;
        const uint32_t soff = (uint32_t)st * STAGE_QKV;

        uint32_t a1[4][4], a2[4][4], bf[4][2];
        #pragma unroll
        for (int mi = 0; mi < 4; ++mi) {
            LDSM4(a1[mi], a_addr[mi] + soff);
            LDSM4(a2[mi], a_addr[mi] + soff + T128);
        }
        #pragma unroll
        for (int p = 0; p < 2; ++p) {
            uint32_t t[4];
            LDSM4(t, b_addr[p] + soff);
            bf[2*p][0] = t[0]; bf[2*p][1] = t[1];
            bf[2*p+1][0] = t[2]; bf[2*p+1][1] = t[3];
        }

        if (ch + 1 < nchunks) store_pf(st ^ 1);
        if (ch + 2 < nchunks) load_pf(ch + 2);

        #pragma unroll
        for (int mi = 0; mi < 4; ++mi)
            #pragma unroll
            for (int ni = 0; ni < 4; ++ni) {
                MMA16816_F16(acc[mi][ni], a1[mi], bf[ni][0], bf[ni][1]);
                MMA16816_F16(acc[mi][ni], a2[mi], bf[ni][0], bf[ni][1]);
            }

        __syncthreads();
    }
}

// ===========================================================================
// 128x256 GEMMs: warp layout 2(M) x 4(N), warp tile 64x64, acc[4][8][4].
// Raw fp16 operand streams.
// ===========================================================================

// Common ldmatrix address setup for the 256-wide B tile at offset boff.
struct Addr256 {
    uint32_t a[4];
    uint32_t b[4];
};
__device__ __forceinline__ Addr256 make_addr256(uint32_t sb, uint32_t boff) {
    const int tid  = threadIdx.x;
    const int lane = tid & 31;
    const int warp = tid >> 5;
    const int wm = (warp >> 2) * 64;
    const int wn = (warp & 3) * 64;
    Addr256 r;
    #pragma unroll
    for (int mi = 0; mi < 4; ++mi)
        r.a[mi] = sb + (uint32_t)((wm + mi * 16 + (lane & 15)) * ROWB
                                  + (lane >> 4) * 16);
    #pragma unroll
    for (int p = 0; p < 4; ++p)
        r.b[p] = sb + boff
               + (uint32_t)((wn + p * 16 + (lane & 7) + ((lane & 16) ? 8 : 0)) * ROWB
                            + ((lane & 8) ? 16 : 0));
    return r;
}

// scores mainloop: acc += (A1+A2)[128xK] @ B[256xK]^T, all fp16 raw.
__device__ __forceinline__ void gemm256_split(const __half* __restrict__ A1,
                                              const __half* __restrict__ A2,
                                              const __half* __restrict__ B,
                                              int lda, int ldb, int nchunks,
                                              float (&acc)[4][8][4]) {
    __shared__ __align__(16) char smem[2 * STAGE_SC];   // 48 KB

    const int tid = threadIdx.x;
    const uint32_t sb = smem_u32(smem);
    Addr256 ad = make_addr256(sb, 2u * T128);

    const int fr = tid >> 1;    // 0..127
    const int fs = tid & 1;     // 16B segment

    uint4 p1, p2, pb0, pb1;

    auto load_pf = [&](int ch) {
        const __half* a1 = A1 + (size_t)ch * BK + (size_t)fr * lda + fs * 8;
        const __half* a2 = A2 + (size_t)ch * BK + (size_t)fr * lda + fs * 8;
        const __half* b  = B  + (size_t)ch * BK + (size_t)fr * ldb + fs * 8;
        p1  = *reinterpret_cast<const uint4*>(a1);
        p2  = *reinterpret_cast<const uint4*>(a2);
        pb0 = *reinterpret_cast<const uint4*>(b);
        pb1 = *reinterpret_cast<const uint4*>(b + (size_t)128 * ldb);
    };

    auto store_pf = [&](int st) {
        char* base = smem + st * STAGE_SC;
        uint32_t off = fr * ROWB + fs * 16;
        *reinterpret_cast<uint4*>(base + off)            = p1;
        *reinterpret_cast<uint4*>(base + T128 + off)     = p2;
        *reinterpret_cast<uint4*>(base + 2 * T128 + off) = pb0;
        *reinterpret_cast<uint4*>(base + 2 * T128 + off + 128 * ROWB) = pb1;
    };

    load_pf(0);
    store_pf(0);
    if (nchunks > 1) load_pf(1);
    __syncthreads();

    #pragma unroll 1
    for (int ch = 0; ch < nchunks; ++ch) {
        const int st = ch & 1;
        const uint32_t soff = (uint32_t)st * STAGE_SC;

        uint32_t a1[4][4], a2[4][4], bf[8][2];
        #pragma unroll
        for (int mi = 0; mi < 4; ++mi) {
            LDSM4(a1[mi], ad.a[mi] + soff);
            LDSM4(a2[mi], ad.a[mi] + soff + T128);
        }
        #pragma unroll
        for (int p = 0; p < 4; ++p) {
            uint32_t t[4];
            LDSM4(t, ad.b[p] + soff);
            bf[2*p][0] = t[0]; bf[2*p][1] = t[1];
            bf[2*p+1][0] = t[2]; bf[2*p+1][1] = t[3];
        }

        if (ch + 1 < nchunks) store_pf(st ^ 1);
        if (ch + 2 < nchunks) load_pf(ch + 2);

        #pragma unroll
        for (int mi = 0; mi < 4; ++mi)
            #pragma unroll
            for (int ni = 0; ni < 8; ++ni) {
                MMA16816_F16(acc[mi][ni], a1[mi], bf[ni][0], bf[ni][1]);
                MMA16816_F16(acc[mi][ni], a2[mi], bf[ni][0], bf[ni][1]);
            }

        __syncthreads();
    }
}

// pv mainloop: acc += P[128xK] @ B[256xK]^T ; P = exp(A - m)*inv on the fly.
__device__ __forceinline__ void gemm256_pv(const __half* __restrict__ A,
                                           const __half* __restrict__ B,
                                           int lda, int ldb, int nchunks,
                                           float (&acc)[4][8][4],
                                           float mrow, float irow) {
    __shared__ __align__(16) char smem[2 * STAGE_PV];   // 36 KB

    const int tid = threadIdx.x;
    const uint32_t sb = smem_u32(smem);
    Addr256 ad = make_addr256(sb, (uint32_t)T128);

    const int fr = tid >> 1;
    const int fs = tid & 1;

    uint4 pa, pb0, pb1;

    auto load_pf = [&](int ch) {
        const __half* a = A + (size_t)ch * BK + (size_t)fr * lda + fs * 8;
        const __half* b = B + (size_t)ch * BK + (size_t)fr * ldb + fs * 8;
        pa  = *reinterpret_cast<const uint4*>(a);
        pb0 = *reinterpret_cast<const uint4*>(b);
        pb1 = *reinterpret_cast<const uint4*>(b + (size_t)128 * ldb);
    };

    auto store_pf = [&](int st) {
        char* base = smem + st * STAGE_PV;
        uint32_t off = fr * ROWB + fs * 16;
        uint32_t w[4] = {pa.x, pa.y, pa.z, pa.w};
        #pragma unroll
        for (int j = 0; j < 4; ++j) {
            __half2 h = *reinterpret_cast<__half2*>(&w[j]);
            float2 f = __half22float2(h);
            f.x = __expf(f.x - mrow) * irow;
            f.y = __expf(f.y - mrow) * irow;
            __half2 o = __floats2half2_rn(f.x, f.y);
            w[j] = *reinterpret_cast<uint32_t*>(&o);
        }
        *reinterpret_cast<uint4*>(base + off) = make_uint4(w[0], w[1], w[2], w[3]);
        *reinterpret_cast<uint4*>(base + T128 + off)              = pb0;
        *reinterpret_cast<uint4*>(base + T128 + off + 128 * ROWB) = pb1;
    };

    load_pf(0);
    store_pf(0);
    if (nchunks > 1) load_pf(1);
    __syncthreads();

    #pragma unroll 1
    for (int ch = 0; ch < nchunks; ++ch) {
        const int st = ch & 1;
        const uint32_t soff = (uint32_t)st * STAGE_PV;

        uint32_t ah[4][4], bf[8][2];
        #pragma unroll
        for (int mi = 0; mi < 4; ++mi)
            LDSM4(ah[mi], ad.a[mi] + soff);
        #pragma unroll
        for (int p = 0; p < 4; ++p) {
            uint32_t t[4];
            LDSM4(t, ad.b[p] + soff);
            bf[2*p][0] = t[0]; bf[2*p][1] = t[1];
            bf[2*p+1][0] = t[2]; bf[2*p+1][1] = t[3];
        }

        if (ch + 1 < nchunks) store_pf(st ^ 1);
        if (ch + 2 < nchunks) load_pf(ch + 2);

        #pragma unroll
        for (int mi = 0; mi < 4; ++mi)
            #pragma unroll
            for (int ni = 0; ni < 8; ++ni)
                MMA16816_F16(acc[mi][ni], ah[mi], bf[ni][0], bf[ni][1]);

        __syncthreads();
    }
}

// Fragment coordinate helpers.
__device__ __forceinline__ int frag_row(int mi) {
    int lane = threadIdx.x & 31, warp = threadIdx.x >> 5;
    return (warp >> 2) * 64 + mi * 16 + (lane >> 2);
}
__device__ __forceinline__ int frag_col32(int ni) {   // 64x32 warp tile
    int lane = threadIdx.x & 31, warp = threadIdx.x >> 5;
    return (warp & 3) * 32 + ni * 8 + 2 * (lane & 3);
}
__device__ __forceinline__ int frag_col64(int ni) {   // 64x64 warp tile
    int lane = threadIdx.x & 31, warp = threadIdx.x >> 5;
    return (warp & 3) * 64 + ni * 8 + 2 * (lane & 3);
}

// ---------------------------------------------------------------------------
// Kernel 1: fused QKV. grid (128, 2, 3); which: 0=Q (hi/lo), 1=K (fp16),
// 2=V (V^T fp16).
// ---------------------------------------------------------------------------
__global__ void __launch_bounds__(THREADS, 1)
qkv_kernel(const float* __restrict__ x,
           const float* __restrict__ wq, const float* __restrict__ bq,
           const float* __restrict__ wk, const float* __restrict__ bk,
           const float* __restrict__ wv, const float* __restrict__ bv) {
    const int mt = blockIdx.x, nt = blockIdx.y, which = blockIdx.z;
    const float* w    = (which == 0) ? wq : (which == 1) ? wk : wv;
    const float* bias = (which == 0) ? bq : (which == 1) ? bk : bv;

    float acc[4][4][4];
    #pragma unroll
    for (int i = 0; i < 4; ++i)
        #pragma unroll
        for (int j = 0; j < 4; ++j)
            #pragma unroll
            for (int r = 0; r < 4; ++r) acc[i][j][r] = 0.f;

    gemm_tile(x + (size_t)mt * 128 * IN_DIM, IN_DIM,
              w + (size_t)nt * 128 * IN_DIM, IN_DIM,
              IN_DIM / BK, acc);

    #pragma unroll
    for (int mi = 0; mi < 4; ++mi)
        #pragma unroll
        for (int ni = 0; ni < 4; ++ni) {
            int m0 = mt * 128 + frag_row(mi);
            int n  = nt * 128 + frag_col32(ni);
            float b0 = __ldg(bias + n), b1 = __ldg(bias + n + 1);
            #pragma unroll
            for (int rr = 0; rr < 2; ++rr) {
                int m = m0 + rr * 8;
                float v0 = acc[mi][ni][2*rr]     + b0;
                float v1 = acc[mi][ni][2*rr + 1] + b1;
                if (which == 2) {
                    int b = m >> 10, s = m & 1023;
                    g_vth[((size_t)b * OUT_DIM + n)     * SEQ + s] = __float2half(v0);
                    g_vth[((size_t)b * OUT_DIM + n + 1) * SEQ + s] = __float2half(v1);
                } else if (which == 1) {
                    __half2 h = __floats2half2_rn(v0, v1);
                    *reinterpret_cast<__half2*>(&g_kh[(size_t)m * OUT_DIM + n]) = h;
                } else {
                    uint32_t hi, lo;
                    split_f16(v0, v1, hi, lo);
                    *reinterpret_cast<uint32_t*>(&g_q1[(size_t)m * OUT_DIM + n]) = hi;
                    *reinterpret_cast<uint32_t*>(&g_q2[(size_t)m * OUT_DIM + n]) = lo;
                }
            }
        }
}

// ---------------------------------------------------------------------------
// Kernel 2: scores = (Q K^T) * SCALE, stored fp16. grid (8 mt, 4 nt, 16 b).
// ---------------------------------------------------------------------------
__global__ void __launch_bounds__(THREADS, 1)
scores_kernel() {
    const int mt = blockIdx.x, nt = blockIdx.y, b = blockIdx.z;
    float acc[4][8][4];
    #pragma unroll
    for (int i = 0; i < 4; ++i)
        #pragma unroll
        for (int j = 0; j < 8; ++j)
            #pragma unroll
            for (int r = 0; r < 4; ++r) acc[i][j][r] = 0.f;

    const size_t arow = ((size_t)b * SEQ + mt * 128) * OUT_DIM;
    const size_t brow = ((size_t)b * SEQ + nt * 256) * OUT_DIM;
    gemm256_split(g_q1 + arow, g_q2 + arow, g_kh + brow,
                  OUT_DIM, OUT_DIM, OUT_DIM / BK, acc);

    #pragma unroll
    for (int mi = 0; mi < 4; ++mi)
        #pragma unroll
        for (int ni = 0; ni < 8; ++ni) {
            int m0 = mt * 128 + frag_row(mi);
            int n  = nt * 256 + frag_col64(ni);
            __half* base = g_sh + (size_t)b * SEQ * SEQ;
            __half2 v0 = __floats2half2_rn(acc[mi][ni][0] * SCALE,
                                           acc[mi][ni][1] * SCALE);
            __half2 v1 = __floats2half2_rn(acc[mi][ni][2] * SCALE,
                                           acc[mi][ni][3] * SCALE);
            *reinterpret_cast<__half2*>(&base[(size_t)m0 * SEQ + n])       = v0;
            *reinterpret_cast<__half2*>(&base[(size_t)(m0 + 8) * SEQ + n]) = v1;
        }
}

// ---------------------------------------------------------------------------
// Kernel 3: row stats from fp16 scores.
// ---------------------------------------------------------------------------
__global__ void __launch_bounds__(THREADS)
rowstats_kernel() {
    __shared__ float red[8];
    const size_t row = blockIdx.x;
    const uint2* p = reinterpret_cast<const uint2*>(g_sh + row * SEQ);
    uint2 u = p[threadIdx.x];
    __half2 h0 = *reinterpret_cast<__half2*>(&u.x);
    __half2 h1 = *reinterpret_cast<__half2*>(&u.y);
    float2 a = __half22float2(h0);
    float2 c = __half22float2(h1);

    float mx = fmaxf(fmaxf(a.x, a.y), fmaxf(c.x, c.y));
    #pragma unroll
    for (int o = 16; o > 0; o >>= 1)
        mx = fmaxf(mx, __shfl_xor_sync(0xFFFFFFFFu, mx, o));
    if ((threadIdx.x & 31) == 0) red[threadIdx.x >> 5] = mx;
    __syncthreads();
    float m2 = red[0];
    #pragma unroll
    for (int i = 1; i < 8; ++i) m2 = fmaxf(m2, red[i]);
    __syncthreads();

    float s = __expf(a.x - m2) + __expf(a.y - m2)
            + __expf(c.x - m2) + __expf(c.y - m2);
    #pragma unroll
    for (int o = 16; o > 0; o >>= 1)
        s += __shfl_xor_sync(0xFFFFFFFFu, s, o);
    if ((threadIdx.x & 31) == 0) red[threadIdx.x >> 5] = s;
    __syncthreads();
    if (threadIdx.x == 0) {
        float tot = 0.f;
        #pragma unroll
        for (int i = 0; i < 8; ++i) tot += red[i];
        g_m[row]   = m2;
        g_inv[row] = 1.0f / tot;
    }
}

// ---------------------------------------------------------------------------
// Kernel 4: out = softmax(S) @ V. grid (8 mt, 16 b); N covers all 256 cols.
// ---------------------------------------------------------------------------
__global__ void __launch_bounds__(THREADS, 1)
pv_kernel(float* __restrict__ out) {
    const int mt = blockIdx.x, b = blockIdx.y;
    float acc[4][8][4];
    #pragma unroll
    for (int i = 0; i < 4; ++i)
        #pragma unroll
        for (int j = 0; j < 8; ++j)
            #pragma unroll
            for (int r = 0; r < 4; ++r) acc[i][j][r] = 0.f;

    const int tid = threadIdx.x;
    const size_t rowbase = (size_t)b * SEQ + mt * 128;
    const float mrow = g_m  [rowbase + (tid >> 1)];
    const float irow = g_inv[rowbase + (tid >> 1)];

    gemm256_pv(g_sh  + ((size_t)b * SEQ + mt * 128) * SEQ,
               g_vth + (size_t)b * OUT_DIM * SEQ,
               SEQ, SEQ, SEQ / BK, acc, mrow, irow);

    #pragma unroll
    for (int mi = 0; mi < 4; ++mi)
        #pragma unroll
        for (int ni = 0; ni < 8; ++ni) {
            int m0r = mt * 128 + frag_row(mi);
            int n   = frag_col64(ni);
            float* base = out + (size_t)b * SEQ * OUT_DIM;
            float2 v0 = make_float2(acc[mi][ni][0], acc[mi][ni][1]);
            float2 v1 = make_float2(acc[mi][ni][2], acc[mi][ni][3]);
            *reinterpret_cast<float2*>(&base[(size_t)m0r * OUT_DIM + n])       = v0;
            *reinterpret_cast<float2*>(&base[(size_t)(m0r + 8) * OUT_DIM + n]) = v1;
        }
}

// ---------------------------------------------------------------------------
// Launcher
// ---------------------------------------------------------------------------
extern "C" void kernel_launch(void* const* d_in, const int* in_sizes, int n_in,
                              void* d_out, int out_size) {
    (void)in_sizes; (void)n_in; (void)out_size;
    const float* x  = (const float*)d_in[0];
    const float* wq = (const float*)d_in[1];
    const float* bq = (const float*)d_in[2];
    const float* wk = (const float*)d_in[3];
    const float* bk = (const float*)d_in[4];
    const float* wv = (const float*)d_in[5];
    const float* bv = (const float*)d_in[6];
    float* out = (float*)d_out;

    qkv_kernel<<<dim3(128, 2, 3), THREADS>>>(x, wq, bq, wk, bk, wv, bv);
    scores_kernel<<<dim3(8, 4, 16), THREADS>>>();
    rowstats_kernel<<<BATCH * SEQ, THREADS>>>();
    pv_kernel<<<dim3(8, 16), THREADS>>>(out);
}

// round 16
// speedup vs baseline: 1.6710x; 1.1834x over previous
#include <cuda_runtime.h>
#include <cuda_fp16.h>
#include <cstdint>

// ---------------------------------------------------------------------------
// Problem: B=16, S=1024, IN=512, OUT=256.
// out = softmax((x Wq^T)(x Wk^T)^T / sqrt(512)) (x Wv^T)
// RoPE uses ONE fixed rotation per dim-pair applied identically to Q and K;
// 2x2 rotations are orthogonal => (Rq).(Rk) = q.k, and V is unroped, so RoPE
// cancels exactly and is skipped.
//
// qkv:    128x256 tile (full OUT_DIM per CTA), fp32 loads, split-A fp16
//         2-pass. Epilogue: q as exact fp16 hi/lo pair, k / V^T as fp16.
// scores: 128x256 tile, raw fp16 streams; epilogue ALSO emits per-CTA
//         row-stat partials (max, sum-exp over its 256 cols).
// reduce: 4 partials -> g_m, g_inv per row (replaces full rowstats pass).
// pv:     128x256 tile, single-pass fp16; softmax folded into A fill.
// ---------------------------------------------------------------------------
#define BATCH   16
#define SEQ     1024
#define IN_DIM  512
#define OUT_DIM 256

#define THREADS 256
#define BK 16              // K elements per chunk

#define ROWB 48            // SMEM row stride bytes (16 elems*2B = 32B + 16B pad)
#define T128 (128 * ROWB)             // 128-row b16 tile: 6144 B
#define T256 (256 * ROWB)             // 256-row b16 tile: 12288 B
#define STAGE_SC  (2 * T128 + T256)   // A1 A2 B256 : 24576 B
#define STAGE_PV  (T128 + T256)       // A B256 : 18432 B

#define SCALE 0.044194173824159216f   // 1/sqrt(512)

// ---------------------------------------------------------------------------
// Scratch (device globals; allocations are forbidden)
// ---------------------------------------------------------------------------
__device__ __half g_q1 [BATCH * SEQ * OUT_DIM];        // q hi (fp16)
__device__ __half g_q2 [BATCH * SEQ * OUT_DIM];        // q lo (fp16), q1+q2==q
__device__ __half g_kh [BATCH * SEQ * OUT_DIM];        // k (fp16)
__device__ __half g_vth[BATCH * OUT_DIM * SEQ];        // [b][d][s]  (V^T fp16)
__device__ __half g_sh [(size_t)BATCH * SEQ * SEQ];    // scaled scores (fp16)
__device__ float  g_pm [BATCH * SEQ * 4];              // partial row max
__device__ float  g_ps [BATCH * SEQ * 4];              // partial sum-exp
__device__ float  g_m  [BATCH * SEQ];                  // row max
__device__ float  g_inv[BATCH * SEQ];                  // 1 / sum(exp(s - m))

// ---------------------------------------------------------------------------
// Helpers
// ---------------------------------------------------------------------------
__device__ __forceinline__ uint32_t smem_u32(const void* p) {
    uint32_t a;
    asm("{ .reg .u64 t; cvta.to.shared.u64 t, %1; cvt.u32.u64 %0, t; }"
        : "=r"(a) : "l"(p));
    return a;
}

#define LDSM4(R, addr) \
    asm volatile("ldmatrix.sync.aligned.m8n8.x4.shared.b16 {%0,%1,%2,%3}, [%4];" \
        : "=r"((R)[0]), "=r"((R)[1]), "=r"((R)[2]), "=r"((R)[3]) : "r"(addr))

#define MMA16816_F16(C, A, B0, B1) \
    asm volatile( \
        "mma.sync.aligned.m16n8k16.row.col.f32.f16.f16.f32 " \
        "{%0,%1,%2,%3}, {%4,%5,%6,%7}, {%8,%9}, {%0,%1,%2,%3};" \
        : "+f"((C)[0]), "+f"((C)[1]), "+f"((C)[2]), "+f"((C)[3]) \
        : "r"((A)[0]), "r"((A)[1]), "r"((A)[2]), "r"((A)[3]), \
          "r"(B0), "r"(B1))

__device__ __forceinline__ void split_f16(float x, float y,
                                          uint32_t& hi, uint32_t& lo) {
    __half2 h = __floats2half2_rn(x, y);
    float2 q = __half22float2(h);
    __half2 l = __floats2half2_rn(x - q.x, y - q.y);
    hi = *reinterpret_cast<uint32_t*>(&h);
    lo = *reinterpret_cast<uint32_t*>(&l);
}

// ldmatrix address setup for 128-row A tiles + 256-row B tile at offset boff.
struct Addr256 {
    uint32_t a[4];
    uint32_t b[4];
};
__device__ __forceinline__ Addr256 make_addr256(uint32_t sb, uint32_t boff) {
    const int tid  = threadIdx.x;
    const int lane = tid & 31;
    const int warp = tid >> 5;
    const int wm = (warp >> 2) * 64;
    const int wn = (warp & 3) * 64;
    Addr256 r;
    #pragma unroll
    for (int mi = 0; mi < 4; ++mi)
        r.a[mi] = sb + (uint32_t)((wm + mi * 16 + (lane & 15)) * ROWB
                                  + (lane >> 4) * 16);
    #pragma unroll
    for (int p = 0; p < 4; ++p)
        r.b[p] = sb + boff
               + (uint32_t)((wn + p * 16 + (lane & 7) + ((lane & 16) ? 8 : 0)) * ROWB
                            + ((lane & 8) ? 16 : 0));
    return r;
}

// Fragment coordinate helpers.
__device__ __forceinline__ int frag_row(int mi) {
    int lane = threadIdx.x & 31, warp = threadIdx.x >> 5;
    return (warp >> 2) * 64 + mi * 16 + (lane >> 2);
}
__device__ __forceinline__ int frag_col64(int ni) {   // 64x64 warp tile
    int lane = threadIdx.x & 31, warp = threadIdx.x >> 5;
    return (warp & 3) * 64 + ni * 8 + 2 * (lane & 3);
}

// ===========================================================================
// qkv mainloop (128x256): A fp32 -> exact fp16 split (a1,a2); B fp32 -> fp16.
// 2-pass MMA. Warp layout 2(M) x 4(N), warp tile 64x64.
// ===========================================================================
__device__ __forceinline__ void gemm256_qkv(const float* __restrict__ A,
                                            const float* __restrict__ B,
                                            int nchunks, float (&acc)[4][8][4]) {
    __shared__ __align__(16) char smem[2 * STAGE_SC];   // 48 KB

    const int tid = threadIdx.x;
    const uint32_t sb = smem_u32(smem);
    Addr256 ad = make_addr256(sb, 2u * T128);

    const int r0 = tid >> 2, f0 = tid & 3;   // A rows r0, r0+64; B rows r0+64i

    float4 pa0, pa1, pb[4];

    auto load_pf = [&](int ch) {
        const float* An = A + (size_t)ch * BK;
        const float* Bn = B + (size_t)ch * BK;
        pa0 = *reinterpret_cast<const float4*>(An + (size_t)r0 * IN_DIM + f0 * 4);
        pa1 = *reinterpret_cast<const float4*>(An + (size_t)(r0 + 64) * IN_DIM + f0 * 4);
        #pragma unroll
        for (int i = 0; i < 4; ++i)
            pb[i] = *reinterpret_cast<const float4*>(
                        Bn + (size_t)(r0 + 64 * i) * IN_DIM + f0 * 4);
    };

    auto store_pf = [&](int st) {
        char* base = smem + st * STAGE_SC;
        #pragma unroll
        for (int i = 0; i < 2; ++i) {
            int r = r0 + 64 * i;
            float4 v = i ? pa1 : pa0;
            uint32_t h0, l0, h1, l1;
            split_f16(v.x, v.y, h0, l0);
            split_f16(v.z, v.w, h1, l1);
            char* dst = base + r * ROWB + f0 * 8;
            *reinterpret_cast<uint2*>(dst)        = make_uint2(h0, h1);
            *reinterpret_cast<uint2*>(dst + T128) = make_uint2(l0, l1);
        }
        #pragma unroll
        for (int i = 0; i < 4; ++i) {
            int r = r0 + 64 * i;
            float4 v = pb[i];
            __half2 h0 = __floats2half2_rn(v.x, v.y);
            __half2 h1 = __floats2half2_rn(v.z, v.w);
            *reinterpret_cast<uint2*>(base + 2 * T128 + r * ROWB + f0 * 8) =
                make_uint2(*reinterpret_cast<uint32_t*>(&h0),
                           *reinterpret_cast<uint32_t*>(&h1));
        }
    };

    load_pf(0);
    store_pf(0);
    if (nchunks > 1) load_pf(1);
    __syncthreads();

    #pragma unroll 1
    for (int ch = 0; ch < nchunks; ++ch) {
        const int st = ch & 1;
        const uint32_t soff = (uint32_t)st * STAGE_SC;

        uint32_t a1[4][4], a2[4][4], bf[8][2];
        #pragma unroll
        for (int mi = 0; mi < 4; ++mi) {
            LDSM4(a1[mi], ad.a[mi] + soff);
            LDSM4(a2[mi], ad.a[mi] + soff + T128);
        }
        #pragma unroll
        for (int p = 0; p < 4; ++p) {
            uint32_t t[4];
            LDSM4(t, ad.b[p] + soff);
            bf[2*p][0] = t[0]; bf[2*p][1] = t[1];
            bf[2*p+1][0] = t[2]; bf[2*p+1][1] = t[3];
        }

        if (ch + 1 < nchunks) store_pf(st ^ 1);
        if (ch + 2 < nchunks) load_pf(ch + 2);

        #pragma unroll
        for (int mi = 0; mi < 4; ++mi)
            #pragma unroll
            for (int ni = 0; ni < 8; ++ni) {
                MMA16816_F16(acc[mi][ni], a1[mi], bf[ni][0], bf[ni][1]);
                MMA16816_F16(acc[mi][ni], a2[mi], bf[ni][0], bf[ni][1]);
            }

        __syncthreads();
    }
}

// ===========================================================================
// scores mainloop: acc += (A1+A2)[128xK] @ B[256xK]^T, all fp16 raw.
// smem passed in so the kernel can reuse it for the stats epilogue.
// ===========================================================================
__device__ __forceinline__ void gemm256_split(const __half* __restrict__ A1,
                                              const __half* __restrict__ A2,
                                              const __half* __restrict__ B,
                                              int lda, int ldb, int nchunks,
                                              float (&acc)[4][8][4],
                                              char* smem) {
    const int tid = threadIdx.x;
    const uint32_t sb = smem_u32(smem);
    Addr256 ad = make_addr256(sb, 2u * T128);

    const int fr = tid >> 1;    // 0..127
    const int fs = tid & 1;     // 16B segment

    uint4 p1, p2, pb0, pb1;

    auto load_pf = [&](int ch) {
        const __half* a1 = A1 + (size_t)ch * BK + (size_t)fr * lda + fs * 8;
        const __half* a2 = A2 + (size_t)ch * BK + (size_t)fr * lda + fs * 8;
        const __half* b  = B  + (size_t)ch * BK + (size_t)fr * ldb + fs * 8;
        p1  = *reinterpret_cast<const uint4*>(a1);
        p2  = *reinterpret_cast<const uint4*>(a2);
        pb0 = *reinterpret_cast<const uint4*>(b);
        pb1 = *reinterpret_cast<const uint4*>(b + (size_t)128 * ldb);
    };

    auto store_pf = [&](int st) {
        char* base = smem + st * STAGE_SC;
        uint32_t off = fr * ROWB + fs * 16;
        *reinterpret_cast<uint4*>(base + off)            = p1;
        *reinterpret_cast<uint4*>(base + T128 + off)     = p2;
        *reinterpret_cast<uint4*>(base + 2 * T128 + off) = pb0;
        *reinterpret_cast<uint4*>(base + 2 * T128 + off + 128 * ROWB) = pb1;
    };

    load_pf(0);
    store_pf(0);
    if (nchunks > 1) load_pf(1);
    __syncthreads();

    #pragma unroll 1
    for (int ch = 0; ch < nchunks; ++ch) {
        const int st = ch & 1;
        const uint32_t soff = (uint32_t)st * STAGE_SC;

        uint32_t a1[4][4], a2[4][4], bf[8][2];
        #pragma unroll
        for (int mi = 0; mi < 4; ++mi) {
            LDSM4(a1[mi], ad.a[mi] + soff);
            LDSM4(a2[mi], ad.a[mi] + soff + T128);
        }
        #pragma unroll
        for (int p = 0; p < 4; ++p) {
            uint32_t t[4];
            LDSM4(t, ad.b[p] + soff);
            bf[2*p][0] = t[0]; bf[2*p][1] = t[1];
            bf[2*p+1][0] = t[2]; bf[2*p+1][1] = t[3];
        }

        if (ch + 1 < nchunks) store_pf(st ^ 1);
        if (ch + 2 < nchunks) load_pf(ch + 2);

        #pragma unroll
        for (int mi = 0; mi < 4; ++mi)
            #pragma unroll
            for (int ni = 0; ni < 8; ++ni) {
                MMA16816_F16(acc[mi][ni], a1[mi], bf[ni][0], bf[ni][1]);
                MMA16816_F16(acc[mi][ni], a2[mi], bf[ni][0], bf[ni][1]);
            }

        __syncthreads();
    }
}

// ===========================================================================
// pv mainloop: acc += P[128xK] @ B[256xK]^T ; P = exp(A - m)*inv on the fly.
// ===========================================================================
__device__ __forceinline__ void gemm256_pv(const __half* __restrict__ A,
                                           const __half* __restrict__ B,
                                           int lda, int ldb, int nchunks,
                                           float (&acc)[4][8][4],
                                           float mrow, float irow) {
    __shared__ __align__(16) char smem[2 * STAGE_PV];   // 36 KB

    const int tid = threadIdx.x;
    const uint32_t sb = smem_u32(smem);
    Addr256 ad = make_addr256(sb, (uint32_t)T128);

    const int fr = tid >> 1;
    const int fs = tid & 1;

    uint4 pa, pb0, pb1;

    auto load_pf = [&](int ch) {
        const __half* a = A + (size_t)ch * BK + (size_t)fr * lda + fs * 8;
        const __half* b = B + (size_t)ch * BK + (size_t)fr * ldb + fs * 8;
        pa  = *reinterpret_cast<const uint4*>(a);
        pb0 = *reinterpret_cast<const uint4*>(b);
        pb1 = *reinterpret_cast<const uint4*>(b + (size_t)128 * ldb);
    };

    auto store_pf = [&](int st) {
        char* base = smem + st * STAGE_PV;
        uint32_t off = fr * ROWB + fs * 16;
        uint32_t w[4] = {pa.x, pa.y, pa.z, pa.w};
        #pragma unroll
        for (int j = 0; j < 4; ++j) {
            __half2 h = *reinterpret_cast<__half2*>(&w[j]);
            float2 f = __half22float2(h);
            f.x = __expf(f.x - mrow) * irow;
            f.y = __expf(f.y - mrow) * irow;
            __half2 o = __floats2half2_rn(f.x, f.y);
            w[j] = *reinterpret_cast<uint32_t*>(&o);
        }
        *reinterpret_cast<uint4*>(base + off) = make_uint4(w[0], w[1], w[2], w[3]);
        *reinterpret_cast<uint4*>(base + T128 + off)              = pb0;
        *reinterpret_cast<uint4*>(base + T128 + off + 128 * ROWB) = pb1;
    };

    load_pf(0);
    store_pf(0);
    if (nchunks > 1) load_pf(1);
    __syncthreads();

    #pragma unroll 1
    for (int ch = 0; ch < nchunks; ++ch) {
        const int st = ch & 1;
        const uint32_t soff = (uint32_t)st * STAGE_PV;

        uint32_t ah[4][4], bf[8][2];
        #pragma unroll
        for (int mi = 0; mi < 4; ++mi)
            LDSM4(ah[mi], ad.a[mi] + soff);
        #pragma unroll
        for (int p = 0; p < 4; ++p) {
            uint32_t t[4];
            LDSM4(t, ad.b[p] + soff);
            bf[2*p][0] = t[0]; bf[2*p][1] = t[1];
            bf[2*p+1][0] = t[2]; bf[2*p+1][1] = t[3];
        }

        if (ch + 1 < nchunks) store_pf(st ^ 1);
        if (ch + 2 < nchunks) load_pf(ch + 2);

        #pragma unroll
        for (int mi = 0; mi < 4; ++mi)
            #pragma unroll
            for (int ni = 0; ni < 8; ++ni)
                MMA16816_F16(acc[mi][ni], ah[mi], bf[ni][0], bf[ni][1]);

        __syncthreads();
    }
}

// ---------------------------------------------------------------------------
// Kernel 1: fused QKV, full OUT_DIM per CTA. grid (128 mt, 3 which).
// which: 0=Q (hi/lo fp16), 1=K (fp16), 2=V (V^T fp16).
// ---------------------------------------------------------------------------
__global__ void __launch_bounds__(THREADS, 1)
qkv_kernel(const float* __restrict__ x,
           const float* __restrict__ wq, const float* __restrict__ bq,
           const float* __restrict__ wk, const float* __restrict__ bk,
           const float* __restrict__ wv, const float* __restrict__ bv) {
    const int mt = blockIdx.x, which = blockIdx.y;
    const float* w    = (which == 0) ? wq : (which == 1) ? wk : wv;
    const float* bias = (which == 0) ? bq : (which == 1) ? bk : bv;

    float acc[4][8][4];
    #pragma unroll
    for (int i = 0; i < 4; ++i)
        #pragma unroll
        for (int j = 0; j < 8; ++j)
            #pragma unroll
            for (int r = 0; r < 4; ++r) acc[i][j][r] = 0.f;

    gemm256_qkv(x + (size_t)mt * 128 * IN_DIM, w, IN_DIM / BK, acc);

    #pragma unroll
    for (int mi = 0; mi < 4; ++mi)
        #pragma unroll
        for (int ni = 0; ni < 8; ++ni) {
            int m0 = mt * 128 + frag_row(mi);
            int n  = frag_col64(ni);
            float b0 = __ldg(bias + n), b1 = __ldg(bias + n + 1);
            #pragma unroll
            for (int rr = 0; rr < 2; ++rr) {
                int m = m0 + rr * 8;
                float v0 = acc[mi][ni][2*rr]     + b0;
                float v1 = acc[mi][ni][2*rr + 1] + b1;
                if (which == 2) {
                    int b = m >> 10, s = m & 1023;
                    g_vth[((size_t)b * OUT_DIM + n)     * SEQ + s] = __float2half(v0);
                    g_vth[((size_t)b * OUT_DIM + n + 1) * SEQ + s] = __float2half(v1);
                } else if (which == 1) {
                    __half2 h = __floats2half2_rn(v0, v1);
                    *reinterpret_cast<__half2*>(&g_kh[(size_t)m * OUT_DIM + n]) = h;
                } else {
                    uint32_t hi, lo;
                    split_f16(v0, v1, hi, lo);
                    *reinterpret_cast<uint32_t*>(&g_q1[(size_t)m * OUT_DIM + n]) = hi;
                    *reinterpret_cast<uint32_t*>(&g_q2[(size_t)m * OUT_DIM + n]) = lo;
                }
            }
        }
}

// ---------------------------------------------------------------------------
// Kernel 2: scores = (Q K^T)*SCALE (fp16) + per-CTA row-stat partials.
// grid (8 mt, 4 nt, 16 b).
// ---------------------------------------------------------------------------
__global__ void __launch_bounds__(THREADS, 1)
scores_kernel() {
    __shared__ __align__(16) char smem[2 * STAGE_SC];   // 48 KB (reused below)

    const int mt = blockIdx.x, nt = blockIdx.y, b = blockIdx.z;
    float acc[4][8][4];
    #pragma unroll
    for (int i = 0; i < 4; ++i)
        #pragma unroll
        for (int j = 0; j < 8; ++j)
            #pragma unroll
            for (int r = 0; r < 4; ++r) acc[i][j][r] = 0.f;

    const size_t arow = ((size_t)b * SEQ + mt * 128) * OUT_DIM;
    const size_t brow = ((size_t)b * SEQ + nt * 256) * OUT_DIM;
    gemm256_split(g_q1 + arow, g_q2 + arow, g_kh + brow,
                  OUT_DIM, OUT_DIM, OUT_DIM / BK, acc, smem);

    const int tid  = threadIdx.x;
    const int lane = tid & 31;
    const int warp = tid >> 5;
    const int wn   = warp & 3;

    // Write fp16 scores; overwrite acc with the fp16-roundtripped values so
    // stats match exactly what pv will exp().
    #pragma unroll
    for (int mi = 0; mi < 4; ++mi)
        #pragma unroll
        for (int ni = 0; ni < 8; ++ni) {
            int m0 = mt * 128 + frag_row(mi);
            int n  = nt * 256 + frag_col64(ni);
            __half* base = g_sh + (size_t)b * SEQ * SEQ;
            __half2 v0 = __floats2half2_rn(acc[mi][ni][0] * SCALE,
                                           acc[mi][ni][1] * SCALE);
            __half2 v1 = __floats2half2_rn(acc[mi][ni][2] * SCALE,
                                           acc[mi][ni][3] * SCALE);
            *reinterpret_cast<__half2*>(&base[(size_t)m0 * SEQ + n])       = v0;
            *reinterpret_cast<__half2*>(&base[(size_t)(m0 + 8) * SEQ + n]) = v1;
            float2 r0 = __half22float2(v0);
            float2 r1 = __half22float2(v1);
            acc[mi][ni][0] = r0.x; acc[mi][ni][1] = r0.y;
            acc[mi][ni][2] = r1.x; acc[mi][ni][3] = r1.y;
        }

    // Stats scratch reuses the (dead) mainloop smem.
    float* s_max = reinterpret_cast<float*>(smem);         // [128][4]
    float* s_sum = s_max + 128 * 4;                        // [128][4]

    // Phase A: per-row max over this CTA's 256 columns.
    #pragma unroll
    for (int mi = 0; mi < 4; ++mi)
        #pragma unroll
        for (int rr = 0; rr < 2; ++rr) {
            float vm = -1e30f;
            #pragma unroll
            for (int ni = 0; ni < 8; ++ni)
                vm = fmaxf(vm, fmaxf(acc[mi][ni][2*rr], acc[mi][ni][2*rr+1]));
            vm = fmaxf(vm, __shfl_xor_sync(0xFFFFFFFFu, vm, 1));
            vm = fmaxf(vm, __shfl_xor_sync(0xFFFFFFFFu, vm, 2));
            int row = (warp >> 2) * 64 + mi * 16 + (lane >> 2) + rr * 8;
            if ((lane & 3) == 0) s_max[row * 4 + wn] = vm;
        }
    __syncthreads();

    // Phase B: per-row sum of exp(v - ctamax).
    #pragma unroll
    for (int mi = 0; mi < 4; ++mi)
        #pragma unroll
        for (int rr = 0; rr < 2; ++rr) {
            int row = (warp >> 2) * 64 + mi * 16 + (lane >> 2) + rr * 8;
            float rm = fmaxf(fmaxf(s_max[row*4+0], s_max[row*4+1]),
                             fmaxf(s_max[row*4+2], s_max[row*4+3]));
            float sum = 0.f;
            #pragma unroll
            for (int ni = 0; ni < 8; ++ni)
                sum += __expf(acc[mi][ni][2*rr]   - rm)
                     + __expf(acc[mi][ni][2*rr+1] - rm);
            sum += __shfl_xor_sync(0xFFFFFFFFu, sum, 1);
            sum += __shfl_xor_sync(0xFFFFFFFFu, sum, 2);
            if ((lane & 3) == 0) s_sum[row * 4 + wn] = sum;
        }
    __syncthreads();

    if (tid < 128) {
        int row = tid;
        float rm = fmaxf(fmaxf(s_max[row*4+0], s_max[row*4+1]),
                         fmaxf(s_max[row*4+2], s_max[row*4+3]));
        float sm = s_sum[row*4+0] + s_sum[row*4+1]
                 + s_sum[row*4+2] + s_sum[row*4+3];
        size_t gr = (size_t)b * SEQ + mt * 128 + row;
        g_pm[gr * 4 + nt] = rm;
        g_ps[gr * 4 + nt] = sm;
    }
}

// ---------------------------------------------------------------------------
// Kernel 3: combine 4 partials per row -> g_m, g_inv. 16384 threads.
// ---------------------------------------------------------------------------
__global__ void __launch_bounds__(THREADS)
reduce_kernel() {
    int row = blockIdx.x * THREADS + threadIdx.x;
    float m0 = g_pm[row*4+0], m1 = g_pm[row*4+1];
    float m2 = g_pm[row*4+2], m3 = g_pm[row*4+3];
    float m = fmaxf(fmaxf(m0, m1), fmaxf(m2, m3));
    float s = g_ps[row*4+0] * __expf(m0 - m)
            + g_ps[row*4+1] * __expf(m1 - m)
            + g_ps[row*4+2] * __expf(m2 - m)
            + g_ps[row*4+3] * __expf(m3 - m);
    g_m[row]   = m;
    g_inv[row] = 1.0f / s;
}

// ---------------------------------------------------------------------------
// Kernel 4: out = softmax(S) @ V. grid (8 mt, 16 b).
// ---------------------------------------------------------------------------
__global__ void __launch_bounds__(THREADS, 1)
pv_kernel(float* __restrict__ out) {
    const int mt = blockIdx.x, b = blockIdx.y;
    float acc[4][8][4];
    #pragma unroll
    for (int i = 0; i < 4; ++i)
        #pragma unroll
        for (int j = 0; j < 8; ++j)
            #pragma unroll
            for (int r = 0; r < 4; ++r) acc[i][j][r] = 0.f;

    const int tid = threadIdx.x;
    const size_t rowbase = (size_t)b * SEQ + mt * 128;
    const float mrow = g_m  [rowbase + (tid >> 1)];
    const float irow = g_inv[rowbase + (tid >> 1)];

    gemm256_pv(g_sh  + ((size_t)b * SEQ + mt * 128) * SEQ,
               g_vth + (size_t)b * OUT_DIM * SEQ,
               SEQ, SEQ, SEQ / BK, acc, mrow, irow);

    #pragma unroll
    for (int mi = 0; mi < 4; ++mi)
        #pragma unroll
        for (int ni = 0; ni < 8; ++ni) {
            int m0r = mt * 128 + frag_row(mi);
            int n   = frag_col64(ni);
            float* base = out + (size_t)b * SEQ * OUT_DIM;
            float2 v0 = make_float2(acc[mi][ni][0], acc[mi][ni][1]);
            float2 v1 = make_float2(acc[mi][ni][2], acc[mi][ni][3]);
            *reinterpret_cast<float2*>(&base[(size_t)m0r * OUT_DIM + n])       = v0;
            *reinterpret_cast<float2*>(&base[(size_t)(m0r + 8) * OUT_DIM + n]) = v1;
        }
}

// ---------------------------------------------------------------------------
// Launcher
// ---------------------------------------------------------------------------
extern "C" void kernel_launch(void* const* d_in, const int* in_sizes, int n_in,
                              void* d_out, int out_size) {
    (void)in_sizes; (void)n_in; (void)out_size;
    const float* x  = (const float*)d_in[0];
    const float* wq = (const float*)d_in[1];
    const float* bq = (const float*)d_in[2];
    const float* wk = (const float*)d_in[3];
    const float* bk = (const float*)d_in[4];
    const float* wv = (const float*)d_in[5];
    const float* bv = (const float*)d_in[6];
    float* out = (float*)d_out;

    qkv_kernel<<<dim3(128, 3), THREADS>>>(x, wq, bq, wk, bk, wv, bv);
    scores_kernel<<<dim3(8, 4, 16), THREADS>>>();
    reduce_kernel<<<BATCH * SEQ / THREADS, THREADS>>>();
    pv_kernel<<<dim3(8, 16), THREADS>>>(out);
}